// round 14
// baseline (speedup 1.0000x reference)
#include <cuda_runtime.h>
#include <cuda_fp16.h>
#include <math.h>

#define NN 20000
#define EE 320000
#define ET (EE + NN)
#define GG 64
#define FULL 0xffffffffu

#define MT (NN / 16)                        // 1250 m-tiles
#define APACK_BLOCKS MT                     // 1250
#define BPACK_BLOCKS 32
#define COUNT_BLOCKS ((EE / 4 + 255) / 256) // 313
#define MMA_BLOCKS ((MT * 4 + 7) / 8)       // 625
#define BUILD_BLOCKS ((EE / 4 + NN + 255) / 256)  // 391
#define AGG_BLOCKS (NN / 4)                 // 5000 (2 warps per node)

// ---------------- scratch ----------------
__device__ __half g_h[NN * 256];
__device__ __half g_x1[NN * 64];
__device__ __half g_h2[NN * 64];
__device__ uint4  g_ap[MT * 8 * 32];
__device__ uint2  g_w1p[8 * 32 * 32];
__device__ float g_asrc[NN * 4];
__device__ float g_adst[NN * 4];
__device__ float g_asrc2[NN * 2];
__device__ float g_adst2[NN * 2];
__device__ int   g_cnt[NN];                 // zero at load; re-zeroed by agg2 tail
__device__ int   g_off[NN + 1];
__device__ int   g_cur[NN];
__device__ int   g_csr[ET];
__device__ float g_sums[GG * 32];
__device__ float g_gcnt[GG];
__device__ int   g_done;

__device__ __forceinline__ float lrelu(float v) { return v > 0.f ? v : 0.2f * v; }
__device__ __forceinline__ float warp_sum(float v) {
#pragma unroll
    for (int o = 16; o > 0; o >>= 1) v += __shfl_xor_sync(FULL, v, o);
    return v;
}
__device__ __forceinline__ unsigned int packh2(float a, float b) {
    half2 h = __floats2half2_rn(a, b);
    return *(unsigned int*)&h;
}
__device__ __forceinline__ void mma16816(float& c0, float& c1, float& c2, float& c3,
                                         unsigned int a0, unsigned int a1,
                                         unsigned int a2, unsigned int a3,
                                         unsigned int b0, unsigned int b1) {
    asm volatile(
        "mma.sync.aligned.m16n8k16.row.col.f32.f16.f16.f32 "
        "{%0,%1,%2,%3}, {%4,%5,%6,%7}, {%8,%9}, {%0,%1,%2,%3};"
        : "+f"(c0), "+f"(c1), "+f"(c2), "+f"(c3)
        : "r"(a0), "r"(a1), "r"(a2), "r"(a3), "r"(b0), "r"(b1));
}

#define SPLAT2(out, f) asm("mov.b64 %0, {%1, %1};" : "=l"(out) : "r"(__float_as_uint(f)))
#define FMA2(acc, a, b) asm("fma.rn.f32x2 %0, %1, %2, %0;" : "+l"(acc) : "l"(a), "l"(b))
#define UNPACK2(lo, hi, in) asm("mov.b64 {%0, %1}, %2;" : "=r"(lo), "=r"(hi) : "l"(in))

// ---------------- prep: pack A frags, pack B frags, degree count ----------
__global__ void k_prep(const float* __restrict__ x, const float* __restrict__ W1,
                       const int* __restrict__ dst, int* __restrict__ cnt) {
    int b = blockIdx.x, t = threadIdx.x;
    if (b < APACK_BLOCKS) {
        int gid = b * 256 + t;
        int lane = gid & 31;
        int ks = (gid >> 5) & 7;
        int mt = gid >> 8;
        int gr = lane >> 2, ct = lane & 3;
        int r0 = mt * 16 + gr;
        const float2* x2 = (const float2*)x;
        float2 p00 = x2[r0 * 64 + ks * 8 + ct];
        float2 p01 = x2[r0 * 64 + ks * 8 + ct + 4];
        float2 p10 = x2[(r0 + 8) * 64 + ks * 8 + ct];
        float2 p11 = x2[(r0 + 8) * 64 + ks * 8 + ct + 4];
        uint4 frag;
        frag.x = packh2(p00.x, p00.y);
        frag.y = packh2(p10.x, p10.y);
        frag.z = packh2(p01.x, p01.y);
        frag.w = packh2(p11.x, p11.y);
        g_ap[(mt * 8 + ks) * 32 + lane] = frag;
    } else if (b < APACK_BLOCKS + BPACK_BLOCKS) {
        int gid = (b - APACK_BLOCKS) * 256 + t;
        int lane = gid & 31;
        int ntg = (gid >> 5) & 31;
        int ks = gid >> 10;
        int gr = lane >> 2, ct = lane & 3;
        int col = ntg * 8 + gr;
        int k0 = ks * 16 + 2 * ct;
        uint2 frag;
        frag.x = packh2(W1[k0 * 256 + col],       W1[(k0 + 1) * 256 + col]);
        frag.y = packh2(W1[(k0 + 8) * 256 + col], W1[(k0 + 9) * 256 + col]);
        g_w1p[(ks * 32 + ntg) * 32 + lane] = frag;
    } else {
        int gid = (b - APACK_BLOCKS - BPACK_BLOCKS) * 256 + t;
        if (gid < EE / 4) {
            int4 d4 = ((const int4*)dst)[gid];
            atomicAdd(&cnt[d4.x], 1);
            atomicAdd(&cnt[d4.y], 1);
            atomicAdd(&cnt[d4.z], 1);
            atomicAdd(&cnt[d4.w], 1);
        }
    }
}

// ---------------- scan (+1 self-loop; zero pooling buffers) ----------------
__global__ void k_scan(const int* __restrict__ cnt, int* __restrict__ off,
                       int* __restrict__ cur, float* __restrict__ sums,
                       float* __restrict__ gcnt) {
    __shared__ int ssum[1024];
    const int CH = 20;
    int t = threadIdx.x;
    sums[t] = 0.f; sums[t + 1024] = 0.f;
    if (t < GG) gcnt[t] = 0.f;
    int base = t * CH;
    int local[CH];
    int s = 0;
#pragma unroll
    for (int j = 0; j < CH; j++) {
        int v = (base + j < NN) ? (cnt[base + j] + 1) : 0;
        local[j] = s;
        s += v;
    }
    ssum[t] = s;
    __syncthreads();
    for (int o = 1; o < 1024; o <<= 1) {
        int v = (t >= o) ? ssum[t - o] : 0;
        __syncthreads();
        ssum[t] += v;
        __syncthreads();
    }
    int pre = ssum[t] - s;
#pragma unroll
    for (int j = 0; j < CH; j++) {
        if (base + j < NN) { off[base + j] = pre + local[j]; cur[base + j] = pre + local[j]; }
    }
    if (t == 1023) off[NN] = ssum[1023];
}

// ---------------- fused: tensor-core GEMM1 + att1  |  CSR build ------------
__global__ void __launch_bounds__(256) k_mma_build(
        const float* __restrict__ as1, const float* __restrict__ ad1,
        __half* __restrict__ h, float* __restrict__ asrc, float* __restrict__ adst,
        const int* __restrict__ src, const int* __restrict__ dst,
        int* __restrict__ cur, int* __restrict__ csr) {
    if (blockIdx.x >= MMA_BLOCKS) {
        int t = (blockIdx.x - MMA_BLOCKS) * 256 + threadIdx.x;
        if (t < EE / 4) {
            int4 s4 = ((const int4*)src)[t];
            int4 d4 = ((const int4*)dst)[t];
            csr[atomicAdd(&cur[d4.x], 1)] = s4.x;
            csr[atomicAdd(&cur[d4.y], 1)] = s4.y;
            csr[atomicAdd(&cur[d4.z], 1)] = s4.z;
            csr[atomicAdd(&cur[d4.w], 1)] = s4.w;
        } else {
            int n = t - EE / 4;
            if (n < NN) csr[atomicAdd(&cur[n], 1)] = n;
        }
        return;
    }

    int gw = blockIdx.x * 8 + (threadIdx.x >> 5);
    int lane = threadIdx.x & 31;
    int mt = gw >> 2;
    int w = gw & 3;
    if (mt >= MT) return;
    int gr = lane >> 2, ct = lane & 3;
    int row0 = mt * 16;

    uint4 a[8];
#pragma unroll
    for (int ks = 0; ks < 8; ks++) a[ks] = g_ap[(mt * 8 + ks) * 32 + lane];

    float sr = 0.f, sr8 = 0.f, dr = 0.f, dr8 = 0.f;
    half2* h2out = (half2*)h;

#pragma unroll
    for (int nt = 0; nt < 8; nt++) {
        int ntg = w * 8 + nt;
        float c0 = 0.f, c1 = 0.f, c2 = 0.f, c3 = 0.f;
#pragma unroll
        for (int ks = 0; ks < 8; ks++) {
            uint2 bfr = g_w1p[(ks * 32 + ntg) * 32 + lane];
            mma16816(c0, c1, c2, c3, a[ks].x, a[ks].y, a[ks].z, a[ks].w,
                     bfr.x, bfr.y);
        }
        h2out[(row0 + gr) * 128 + w * 32 + nt * 4 + ct]     = __floats2half2_rn(c0, c1);
        h2out[(row0 + gr + 8) * 128 + w * 32 + nt * 4 + ct] = __floats2half2_rn(c2, c3);
        float2 av = ((const float2*)as1)[w * 32 + nt * 4 + ct];
        float2 dv = ((const float2*)ad1)[w * 32 + nt * 4 + ct];
        sr  += c0 * av.x + c1 * av.y;
        sr8 += c2 * av.x + c3 * av.y;
        dr  += c0 * dv.x + c1 * dv.y;
        dr8 += c2 * dv.x + c3 * dv.y;
    }
    sr  += __shfl_xor_sync(FULL, sr, 1);  sr  += __shfl_xor_sync(FULL, sr, 2);
    sr8 += __shfl_xor_sync(FULL, sr8, 1); sr8 += __shfl_xor_sync(FULL, sr8, 2);
    dr  += __shfl_xor_sync(FULL, dr, 1);  dr  += __shfl_xor_sync(FULL, dr, 2);
    dr8 += __shfl_xor_sync(FULL, dr8, 1); dr8 += __shfl_xor_sync(FULL, dr8, 2);
    if (ct == 0) {
        asrc[(row0 + gr) * 4 + w] = sr;
        asrc[(row0 + gr + 8) * 4 + w] = sr8;
        adst[(row0 + gr) * 4 + w] = dr;
        adst[(row0 + gr + 8) * 4 + w] = dr8;
    }
}

// ---------------- layer 1 aggregation: 2 warps per node -> x1 fp16 ---------
__global__ void k_agg1(const int* __restrict__ off, const int* __restrict__ csr,
                       const __half* __restrict__ hfeat, const float* __restrict__ asrc,
                       const float* __restrict__ adst, const float* __restrict__ bias,
                       __half* __restrict__ x1out) {
    __shared__ int    sm_s[8][32];
    __shared__ float4 sm_w[8][32];
    __shared__ float  sm_acc[4][8][33];   // warp1 partial accumulators
    __shared__ float4 sm_den[4];          // warp1 partial denominators
    int wid = threadIdx.x >> 5;
    int lane = threadIdx.x & 31;
    int nl = wid >> 1;                    // local node 0..3
    int wp = wid & 1;                     // edge-half
    int d = blockIdx.x * 4 + nl;          // NN % 4 == 0, always valid

    int b0 = off[d], b1 = off[d + 1];
    int deg = b1 - b0;
    int mid = b0 + ((deg + 1) >> 1);
    int e0 = wp ? mid : b0;
    int e1 = wp ? b1 : mid;

    float4 adv = ((const float4*)adst)[d];
    int hh = lane >> 3;

    float s0 = 0.f, s1 = 0.f, s2 = 0.f, s3 = 0.f;
    float acc[8];
#pragma unroll
    for (int j = 0; j < 8; j++) acc[j] = 0.f;

    const uint4* hf = (const uint4*)hfeat;
    const float4* as4 = (const float4*)asrc;
    const float* wpp = (const float*)&sm_w[wid][0];

    for (int base = e0; base < e1; base += 32) {
        int k = base + lane;
        float4 w = make_float4(0.f, 0.f, 0.f, 0.f);
        int sidx = 0;
        if (k < e1) {
            sidx = csr[k];
            float4 a = as4[sidx];
            w.x = __expf(lrelu(a.x + adv.x));
            w.y = __expf(lrelu(a.y + adv.y));
            w.z = __expf(lrelu(a.z + adv.z));
            w.w = __expf(lrelu(a.w + adv.w));
            s0 += w.x; s1 += w.y; s2 += w.z; s3 += w.w;
        }
        sm_s[wid][lane] = sidx;
        sm_w[wid][lane] = w;
        __syncwarp();
        int cnt = min(32, e1 - base);
        for (int e = 0; e < cnt; e++) {
            int ss = sm_s[wid][e];
            float we = wpp[e * 4 + hh];
            uint4 v = hf[ss * 32 + lane];
            float2 p;
            p = __half22float2(*(half2*)&v.x); acc[0] = fmaf(we, p.x, acc[0]); acc[1] = fmaf(we, p.y, acc[1]);
            p = __half22float2(*(half2*)&v.y); acc[2] = fmaf(we, p.x, acc[2]); acc[3] = fmaf(we, p.y, acc[3]);
            p = __half22float2(*(half2*)&v.z); acc[4] = fmaf(we, p.x, acc[4]); acc[5] = fmaf(we, p.y, acc[5]);
            p = __half22float2(*(half2*)&v.w); acc[6] = fmaf(we, p.x, acc[6]); acc[7] = fmaf(we, p.y, acc[7]);
        }
        __syncwarp();
    }

    s0 = warp_sum(s0); s1 = warp_sum(s1); s2 = warp_sum(s2); s3 = warp_sum(s3);

    if (wp == 1) {
#pragma unroll
        for (int j = 0; j < 8; j++) sm_acc[nl][j][lane] = acc[j];
        if (lane == 0) sm_den[nl] = make_float4(s0, s1, s2, s3);
    }
    __syncthreads();
    if (wp == 1) return;

#pragma unroll
    for (int j = 0; j < 8; j++) acc[j] += sm_acc[nl][j][lane];
    float4 pd = sm_den[nl];
    s0 += pd.x; s1 += pd.y; s2 += pd.z; s3 += pd.w;

    float iH = (hh == 0) ? 1.f / (s0 + 1e-16f)
             : (hh == 1) ? 1.f / (s1 + 1e-16f)
             : (hh == 2) ? 1.f / (s2 + 1e-16f)
             :             1.f / (s3 + 1e-16f);
#pragma unroll
    for (int j = 0; j < 8; j++) acc[j] *= iH;

#pragma unroll
    for (int j = 0; j < 8; j++) {
        acc[j] += __shfl_xor_sync(FULL, acc[j], 8);
        acc[j] += __shfl_xor_sync(FULL, acc[j], 16);
    }
    if (lane < 8) {
        float4 bb0 = ((const float4*)bias)[lane * 2];
        float4 bb1 = ((const float4*)bias)[lane * 2 + 1];
        uint4 pk;
        pk.x = packh2(fmaxf(acc[0] * 0.25f + bb0.x, 0.f), fmaxf(acc[1] * 0.25f + bb0.y, 0.f));
        pk.y = packh2(fmaxf(acc[2] * 0.25f + bb0.z, 0.f), fmaxf(acc[3] * 0.25f + bb0.w, 0.f));
        pk.z = packh2(fmaxf(acc[4] * 0.25f + bb1.x, 0.f), fmaxf(acc[5] * 0.25f + bb1.y, 0.f));
        pk.w = packh2(fmaxf(acc[6] * 0.25f + bb1.z, 0.f), fmaxf(acc[7] * 0.25f + bb1.w, 0.f));
        ((uint4*)x1out)[d * 8 + lane] = pk;
    }
}

// ---------------- GEMM2: 128 nodes/block, 4-node W amortization ------------
__global__ void __launch_bounds__(256) k_gemm2(
        const __half* __restrict__ x1, const float* __restrict__ W2,
        const float* __restrict__ as2, const float* __restrict__ ad2,
        __half* __restrict__ h2out, float* __restrict__ asrc2,
        float* __restrict__ adst2) {
    __shared__ float  smW[64 * 64];
    __shared__ __half smX[128 * 68];
    int t = threadIdx.x;
    int n0 = blockIdx.x * 128;

#pragma unroll
    for (int i = 0; i < 4; i++)
        ((float4*)smW)[t + 256 * i] = ((const float4*)W2)[t + 256 * i];
    {
        int row = t >> 1, part = t & 1;
        int n = n0 + row;
        const uint4* gsrc = (const uint4*)x1 + (long long)n * 8 + part * 4;
        uint2* drow = (uint2*)(smX + row * 68 + part * 32);
#pragma unroll
        for (int i = 0; i < 4; i++) {
            uint4 v = (n < NN) ? gsrc[i] : make_uint4(0, 0, 0, 0);
            drow[2 * i]     = make_uint2(v.x, v.y);
            drow[2 * i + 1] = make_uint2(v.z, v.w);
        }
    }
    __syncthreads();

    int grp = t >> 3;
    int cg  = t & 7;
    int nl0 = grp * 4;

    unsigned long long acc[4][4];
#pragma unroll
    for (int r = 0; r < 4; r++)
#pragma unroll
        for (int j = 0; j < 4; j++) acc[r][j] = 0ull;

    const ulonglong2* Wr = (const ulonglong2*)smW;
#pragma unroll 4
    for (int k = 0; k < 64; k++) {
        ulonglong2 w0 = Wr[k * 16 + cg * 2];
        ulonglong2 w1 = Wr[k * 16 + cg * 2 + 1];
#pragma unroll
        for (int r = 0; r < 4; r++) {
            float xv = __half2float(smX[(nl0 + r) * 68 + k]);
            unsigned long long xs; SPLAT2(xs, xv);
            FMA2(acc[r][0], xs, w0.x); FMA2(acc[r][1], xs, w0.y);
            FMA2(acc[r][2], xs, w1.x); FMA2(acc[r][3], xs, w1.y);
        }
    }

    int hd = cg >> 2;
    const float4* a4 = (const float4*)(as2 + hd * 32 + (cg & 3) * 8);
    const float4* d4v = (const float4*)(ad2 + hd * 32 + (cg & 3) * 8);
    float4 aa0 = a4[0], aa1 = a4[1];
    float4 dd0 = d4v[0], dd1 = d4v[1];

#pragma unroll
    for (int r = 0; r < 4; r++) {
        int d = n0 + nl0 + r;
        float c[8];
        unsigned int lo, hi;
        UNPACK2(lo, hi, acc[r][0]); c[0] = __uint_as_float(lo); c[1] = __uint_as_float(hi);
        UNPACK2(lo, hi, acc[r][1]); c[2] = __uint_as_float(lo); c[3] = __uint_as_float(hi);
        UNPACK2(lo, hi, acc[r][2]); c[4] = __uint_as_float(lo); c[5] = __uint_as_float(hi);
        UNPACK2(lo, hi, acc[r][3]); c[6] = __uint_as_float(lo); c[7] = __uint_as_float(hi);
        float ps = c[0]*aa0.x + c[1]*aa0.y + c[2]*aa0.z + c[3]*aa0.w
                 + c[4]*aa1.x + c[5]*aa1.y + c[6]*aa1.z + c[7]*aa1.w;
        float pd = c[0]*dd0.x + c[1]*dd0.y + c[2]*dd0.z + c[3]*dd0.w
                 + c[4]*dd1.x + c[5]*dd1.y + c[6]*dd1.z + c[7]*dd1.w;
        ps += __shfl_xor_sync(FULL, ps, 1);
        ps += __shfl_xor_sync(FULL, ps, 2);
        pd += __shfl_xor_sync(FULL, pd, 1);
        pd += __shfl_xor_sync(FULL, pd, 2);
        if (d < NN) {
            uint4 pk;
            pk.x = packh2(c[0], c[1]);
            pk.y = packh2(c[2], c[3]);
            pk.z = packh2(c[4], c[5]);
            pk.w = packh2(c[6], c[7]);
            ((uint4*)h2out)[d * 8 + cg] = pk;
            if ((cg & 3) == 0) {
                asrc2[d * 2 + hd] = ps;
                adst2[d * 2 + hd] = pd;
            }
        }
    }
}

// ---------------- layer 2 aggregation (2 warps/node) + pool + heads --------
__global__ void k_agg2(const int* __restrict__ off, const int* __restrict__ csr,
                       const __half* __restrict__ hfeat, const float* __restrict__ asrc,
                       const float* __restrict__ adst, const float* __restrict__ bias,
                       const int* __restrict__ batch, float* __restrict__ sums,
                       float* __restrict__ gcnt,
                       const float* __restrict__ cW1, const float* __restrict__ cb1,
                       const float* __restrict__ cW2, const float* __restrict__ cb2,
                       const float* __restrict__ hW1, const float* __restrict__ hb1,
                       const float* __restrict__ hW2, const float* __restrict__ hb2,
                       float* __restrict__ out, int* __restrict__ cntz,
                       int* __restrict__ done) {
    __shared__ int    sm_s[8][32];
    __shared__ float2 sm_w[8][32];
    __shared__ float  sm_acc[4][2][33];
    __shared__ float2 sm_den[4];
    __shared__ int sm_last;
    int wid = threadIdx.x >> 5;
    int lane = threadIdx.x & 31;
    int nl = wid >> 1;
    int wp = wid & 1;
    int d = blockIdx.x * 4 + nl;

    int b0 = off[d], b1 = off[d + 1];
    int deg = b1 - b0;
    int mid = b0 + ((deg + 1) >> 1);
    int e0 = wp ? mid : b0;
    int e1 = wp ? b1 : mid;

    float2 adv = ((const float2*)adst)[d];
    int hh = lane >> 4;

    float s0 = 0.f, s1 = 0.f;
    float2 acc = make_float2(0.f, 0.f);
    const half2* hf = (const half2*)hfeat;
    const float2* as2p = (const float2*)asrc;
    const float* wpp = (const float*)&sm_w[wid][0];

    for (int base = e0; base < e1; base += 32) {
        int k = base + lane;
        float2 w = make_float2(0.f, 0.f);
        int sidx = 0;
        if (k < e1) {
            sidx = csr[k];
            float2 a = as2p[sidx];
            w.x = __expf(lrelu(a.x + adv.x));
            w.y = __expf(lrelu(a.y + adv.y));
            s0 += w.x; s1 += w.y;
        }
        sm_s[wid][lane] = sidx;
        sm_w[wid][lane] = w;
        __syncwarp();
        int cnt = min(32, e1 - base);
        for (int e = 0; e < cnt; e++) {
            int ss = sm_s[wid][e];
            float we = wpp[e * 2 + hh];
            float2 v = __half22float2(hf[ss * 32 + lane]);
            acc.x = fmaf(we, v.x, acc.x);
            acc.y = fmaf(we, v.y, acc.y);
        }
        __syncwarp();
    }

    s0 = warp_sum(s0); s1 = warp_sum(s1);

    if (wp == 1) {
        sm_acc[nl][0][lane] = acc.x;
        sm_acc[nl][1][lane] = acc.y;
        if (lane == 0) sm_den[nl] = make_float2(s0, s1);
    }
    __syncthreads();

    if (wp == 0) {
        acc.x += sm_acc[nl][0][lane];
        acc.y += sm_acc[nl][1][lane];
        float2 pdn = sm_den[nl];
        s0 += pdn.x; s1 += pdn.y;
        float iH = hh ? 1.f / (s1 + 1e-16f) : 1.f / (s0 + 1e-16f);
        acc.x *= iH;
        acc.y *= iH;
        acc.x += __shfl_xor_sync(FULL, acc.x, 16);
        acc.y += __shfl_xor_sync(FULL, acc.y, 16);
        if (lane < 16) {
            const float2 b = ((const float2*)bias)[lane];
            float ox = fmaxf(acc.x * 0.5f + b.x, 0.f);
            float oy = fmaxf(acc.y * 0.5f + b.y, 0.f);
            int g = batch[d];
            atomicAdd(&sums[g * 32 + 2 * lane], ox);
            atomicAdd(&sums[g * 32 + 2 * lane + 1], oy);
            if (lane == 0) atomicAdd(&gcnt[g], 1.f);
        }
    }

    // ---- last-block-done: fused heads ----
    __threadfence();
    __syncthreads();
    if (threadIdx.x == 0)
        sm_last = (atomicAdd(done, 1) == gridDim.x - 1) ? 1 : 0;
    __syncthreads();
    if (!sm_last) return;

    int t = threadIdx.x;
    int4 z = make_int4(0, 0, 0, 0);
    for (int i = t; i < NN / 4; i += 256) ((int4*)cntz)[i] = z;
    if (t == 0) *done = 0;

    if (t < GG) {
        int g = t;
        float emb[32];
        float c_ = __ldcg(&gcnt[g]);
        c_ = (c_ > 1.f) ? c_ : 1.f;
        for (int c = 0; c < 32; c++) emb[c] = __ldcg(&sums[g * 32 + c]) / c_;
        float oh = hb2[0], oc = cb2[0];
        for (int j = 0; j < 16; j++) {
            float sh = hb1[j], sc = cb1[j];
            for (int c = 0; c < 32; c++) {
                sh = fmaf(emb[c], hW1[c * 16 + j], sh);
                sc = fmaf(emb[c], cW1[c * 16 + j], sc);
            }
            sh = fmaxf(sh, 0.f);
            sc = fmaxf(sc, 0.f);
            oh = fmaf(sh, hW2[j], oh);
            oc = fmaf(sc, cW2[j], oc);
        }
        out[g]      = 1.f / (1.f + __expf(-oh));
        out[GG + g] = 1.f / (1.f + __expf(-oc));
    }
}

// ---------------- host ----------------
static inline int cdiv(long long a, int b) { return (int)((a + b - 1) / b); }

extern "C" void kernel_launch(void* const* d_in, const int* in_sizes, int n_in,
                              void* d_out, int out_size) {
    const float* x     = (const float*)d_in[0];
    const int*   ei    = (const int*)  d_in[1];
    const int*   batch = (const int*)  d_in[2];
    const float* W1  = (const float*)d_in[3];
    const float* as1 = (const float*)d_in[4];
    const float* ad1 = (const float*)d_in[5];
    const float* b1  = (const float*)d_in[6];
    const float* W2  = (const float*)d_in[7];
    const float* as2 = (const float*)d_in[8];
    const float* ad2 = (const float*)d_in[9];
    const float* b2  = (const float*)d_in[10];
    const float* cW1 = (const float*)d_in[11];
    const float* cb1 = (const float*)d_in[12];
    const float* cW2 = (const float*)d_in[13];
    const float* cb2 = (const float*)d_in[14];
    const float* hW1 = (const float*)d_in[15];
    const float* hb1 = (const float*)d_in[16];
    const float* hW2 = (const float*)d_in[17];
    const float* hb2 = (const float*)d_in[18];

    const int* src = ei;
    const int* dst = ei + EE;

    __half *p_h, *p_x1, *p_h2;
    float *p_asrc, *p_adst, *p_asrc2, *p_adst2, *p_sums, *p_gcnt;
    int *p_cnt, *p_off, *p_cur, *p_csr, *p_done;
    cudaGetSymbolAddress((void**)&p_h, g_h);
    cudaGetSymbolAddress((void**)&p_x1, g_x1);
    cudaGetSymbolAddress((void**)&p_h2, g_h2);
    cudaGetSymbolAddress((void**)&p_asrc, g_asrc);
    cudaGetSymbolAddress((void**)&p_adst, g_adst);
    cudaGetSymbolAddress((void**)&p_asrc2, g_asrc2);
    cudaGetSymbolAddress((void**)&p_adst2, g_adst2);
    cudaGetSymbolAddress((void**)&p_cnt, g_cnt);
    cudaGetSymbolAddress((void**)&p_off, g_off);
    cudaGetSymbolAddress((void**)&p_cur, g_cur);
    cudaGetSymbolAddress((void**)&p_csr, g_csr);
    cudaGetSymbolAddress((void**)&p_sums, g_sums);
    cudaGetSymbolAddress((void**)&p_gcnt, g_gcnt);
    cudaGetSymbolAddress((void**)&p_done, g_done);

    const int T = 256;

    k_prep<<<APACK_BLOCKS + BPACK_BLOCKS + COUNT_BLOCKS, T>>>(x, W1, dst, p_cnt);
    k_scan<<<1, 1024>>>(p_cnt, p_off, p_cur, p_sums, p_gcnt);
    k_mma_build<<<MMA_BLOCKS + BUILD_BLOCKS, T>>>(as1, ad1, p_h, p_asrc, p_adst,
                                                  src, dst, p_cur, p_csr);
    k_agg1<<<AGG_BLOCKS, T>>>(p_off, p_csr, p_h, p_asrc, p_adst, b1, p_x1);
    k_gemm2<<<cdiv(NN, 128), T>>>(p_x1, W2, as2, ad2, p_h2, p_asrc2, p_adst2);
    k_agg2<<<AGG_BLOCKS, T>>>(p_off, p_csr, p_h2, p_asrc2, p_adst2, b2,
                              batch, p_sums, p_gcnt,
                              cW1, cb1, cW2, cb2, hW1, hb1, hW2, hb2,
                              (float*)d_out, p_cnt, p_done);
}

// round 15
// speedup vs baseline: 1.2061x; 1.2061x over previous
#include <cuda_runtime.h>
#include <cuda_fp16.h>
#include <math.h>

#define NN 20000
#define EE 320000
#define ET (EE + NN)
#define GG 64
#define FULL 0xffffffffu
#define WSCALE 0.015625f        // 2^-6: keeps fp16 accumulators far from overflow
#define WUNSCALE 64.f

#define MT (NN / 16)
#define APACK_BLOCKS MT
#define BPACK_BLOCKS 32
#define COUNT_BLOCKS ((EE / 4 + 255) / 256)
#define MMA_BLOCKS ((MT * 4 + 7) / 8)
#define BUILD_BLOCKS ((EE / 4 + NN + 255) / 256)
#define AGG_BLOCKS ((NN + 7) / 8)

// ---------------- scratch ----------------
__device__ __half g_h[NN * 256];
__device__ __half g_x1[NN * 64];
__device__ __half g_h2[NN * 64];
__device__ uint4  g_ap[MT * 8 * 32];
__device__ uint2  g_w1p[8 * 32 * 32];
__device__ float g_asrc[NN * 4];
__device__ float g_adst[NN * 4];
__device__ float g_asrc2[NN * 2];
__device__ float g_adst2[NN * 2];
__device__ int   g_cnt[NN];
__device__ int   g_off[NN + 1];
__device__ int   g_cur[NN];
__device__ int   g_csr[ET];
__device__ float g_sums[GG * 32];
__device__ float g_gcnt[GG];
__device__ int   g_done;

__device__ __forceinline__ float lrelu(float v) { return v > 0.f ? v : 0.2f * v; }
__device__ __forceinline__ float warp_sum(float v) {
#pragma unroll
    for (int o = 16; o > 0; o >>= 1) v += __shfl_xor_sync(FULL, v, o);
    return v;
}
__device__ __forceinline__ unsigned int packh2(float a, float b) {
    half2 h = __floats2half2_rn(a, b);
    return *(unsigned int*)&h;
}
__device__ __forceinline__ unsigned int splath2(float a) {
    half2 h = __float2half2_rn(a);
    return *(unsigned int*)&h;
}
__device__ __forceinline__ void mma16816(float& c0, float& c1, float& c2, float& c3,
                                         unsigned int a0, unsigned int a1,
                                         unsigned int a2, unsigned int a3,
                                         unsigned int b0, unsigned int b1) {
    asm volatile(
        "mma.sync.aligned.m16n8k16.row.col.f32.f16.f16.f32 "
        "{%0,%1,%2,%3}, {%4,%5,%6,%7}, {%8,%9}, {%0,%1,%2,%3};"
        : "+f"(c0), "+f"(c1), "+f"(c2), "+f"(c3)
        : "r"(a0), "r"(a1), "r"(a2), "r"(a3), "r"(b0), "r"(b1));
}

#define HFMA2(acc, a, b) asm("fma.rn.f16x2 %0, %1, %2, %0;" : "+r"(acc) : "r"(a), "r"(b))
#define SPLAT2(out, f) asm("mov.b64 %0, {%1, %1};" : "=l"(out) : "r"(__float_as_uint(f)))
#define FMA2(acc, a, b) asm("fma.rn.f32x2 %0, %1, %2, %0;" : "+l"(acc) : "l"(a), "l"(b))
#define UNPACK2(lo, hi, in) asm("mov.b64 {%0, %1}, %2;" : "=r"(lo), "=r"(hi) : "l"(in))

__device__ __forceinline__ float2 h2f2(unsigned int u) {
    return __half22float2(*(half2*)&u);
}

// ---------------- prep: pack A frags, pack B frags, degree count ----------
__global__ void k_prep(const float* __restrict__ x, const float* __restrict__ W1,
                       const int* __restrict__ dst, int* __restrict__ cnt) {
    int b = blockIdx.x, t = threadIdx.x;
    if (b < APACK_BLOCKS) {
        int gid = b * 256 + t;
        int lane = gid & 31;
        int ks = (gid >> 5) & 7;
        int mt = gid >> 8;
        int gr = lane >> 2, ct = lane & 3;
        int r0 = mt * 16 + gr;
        const float2* x2 = (const float2*)x;
        float2 p00 = x2[r0 * 64 + ks * 8 + ct];
        float2 p01 = x2[r0 * 64 + ks * 8 + ct + 4];
        float2 p10 = x2[(r0 + 8) * 64 + ks * 8 + ct];
        float2 p11 = x2[(r0 + 8) * 64 + ks * 8 + ct + 4];
        uint4 frag;
        frag.x = packh2(p00.x, p00.y);
        frag.y = packh2(p10.x, p10.y);
        frag.z = packh2(p01.x, p01.y);
        frag.w = packh2(p11.x, p11.y);
        g_ap[(mt * 8 + ks) * 32 + lane] = frag;
    } else if (b < APACK_BLOCKS + BPACK_BLOCKS) {
        int gid = (b - APACK_BLOCKS) * 256 + t;
        int lane = gid & 31;
        int ntg = (gid >> 5) & 31;
        int ks = gid >> 10;
        int gr = lane >> 2, ct = lane & 3;
        int col = ntg * 8 + gr;
        int k0 = ks * 16 + 2 * ct;
        uint2 frag;
        frag.x = packh2(W1[k0 * 256 + col],       W1[(k0 + 1) * 256 + col]);
        frag.y = packh2(W1[(k0 + 8) * 256 + col], W1[(k0 + 9) * 256 + col]);
        g_w1p[(ks * 32 + ntg) * 32 + lane] = frag;
    } else {
        int gid = (b - APACK_BLOCKS - BPACK_BLOCKS) * 256 + t;
        if (gid < EE / 4) {
            int4 d4 = ((const int4*)dst)[gid];
            atomicAdd(&cnt[d4.x], 1);
            atomicAdd(&cnt[d4.y], 1);
            atomicAdd(&cnt[d4.z], 1);
            atomicAdd(&cnt[d4.w], 1);
        }
    }
}

// ---------------- scan (+1 self-loop; zero pooling buffers) ----------------
__global__ void k_scan(const int* __restrict__ cnt, int* __restrict__ off,
                       int* __restrict__ cur, float* __restrict__ sums,
                       float* __restrict__ gcnt) {
    __shared__ int ssum[1024];
    const int CH = 20;
    int t = threadIdx.x;
    sums[t] = 0.f; sums[t + 1024] = 0.f;
    if (t < GG) gcnt[t] = 0.f;
    int base = t * CH;
    int local[CH];
    int s = 0;
#pragma unroll
    for (int j = 0; j < CH; j++) {
        int v = (base + j < NN) ? (cnt[base + j] + 1) : 0;
        local[j] = s;
        s += v;
    }
    ssum[t] = s;
    __syncthreads();
    for (int o = 1; o < 1024; o <<= 1) {
        int v = (t >= o) ? ssum[t - o] : 0;
        __syncthreads();
        ssum[t] += v;
        __syncthreads();
    }
    int pre = ssum[t] - s;
#pragma unroll
    for (int j = 0; j < CH; j++) {
        if (base + j < NN) { off[base + j] = pre + local[j]; cur[base + j] = pre + local[j]; }
    }
    if (t == 1023) off[NN] = ssum[1023];
}

// ---------------- fused: tensor-core GEMM1 + att1  |  CSR build ------------
__global__ void __launch_bounds__(256) k_mma_build(
        const float* __restrict__ as1, const float* __restrict__ ad1,
        __half* __restrict__ h, float* __restrict__ asrc, float* __restrict__ adst,
        const int* __restrict__ src, const int* __restrict__ dst,
        int* __restrict__ cur, int* __restrict__ csr) {
    if (blockIdx.x >= MMA_BLOCKS) {
        int t = (blockIdx.x - MMA_BLOCKS) * 256 + threadIdx.x;
        if (t < EE / 4) {
            int4 s4 = ((const int4*)src)[t];
            int4 d4 = ((const int4*)dst)[t];
            csr[atomicAdd(&cur[d4.x], 1)] = s4.x;
            csr[atomicAdd(&cur[d4.y], 1)] = s4.y;
            csr[atomicAdd(&cur[d4.z], 1)] = s4.z;
            csr[atomicAdd(&cur[d4.w], 1)] = s4.w;
        } else {
            int n = t - EE / 4;
            if (n < NN) csr[atomicAdd(&cur[n], 1)] = n;
        }
        return;
    }

    int gw = blockIdx.x * 8 + (threadIdx.x >> 5);
    int lane = threadIdx.x & 31;
    int mt = gw >> 2;
    int w = gw & 3;
    if (mt >= MT) return;
    int gr = lane >> 2, ct = lane & 3;
    int row0 = mt * 16;

    uint4 a[8];
#pragma unroll
    for (int ks = 0; ks < 8; ks++) a[ks] = g_ap[(mt * 8 + ks) * 32 + lane];

    float sr = 0.f, sr8 = 0.f, dr = 0.f, dr8 = 0.f;
    half2* h2out = (half2*)h;

#pragma unroll
    for (int nt = 0; nt < 8; nt++) {
        int ntg = w * 8 + nt;
        float c0 = 0.f, c1 = 0.f, c2 = 0.f, c3 = 0.f;
#pragma unroll
        for (int ks = 0; ks < 8; ks++) {
            uint2 bfr = g_w1p[(ks * 32 + ntg) * 32 + lane];
            mma16816(c0, c1, c2, c3, a[ks].x, a[ks].y, a[ks].z, a[ks].w,
                     bfr.x, bfr.y);
        }
        h2out[(row0 + gr) * 128 + w * 32 + nt * 4 + ct]     = __floats2half2_rn(c0, c1);
        h2out[(row0 + gr + 8) * 128 + w * 32 + nt * 4 + ct] = __floats2half2_rn(c2, c3);
        float2 av = ((const float2*)as1)[w * 32 + nt * 4 + ct];
        float2 dv = ((const float2*)ad1)[w * 32 + nt * 4 + ct];
        sr  += c0 * av.x + c1 * av.y;
        sr8 += c2 * av.x + c3 * av.y;
        dr  += c0 * dv.x + c1 * dv.y;
        dr8 += c2 * dv.x + c3 * dv.y;
    }
    sr  += __shfl_xor_sync(FULL, sr, 1);  sr  += __shfl_xor_sync(FULL, sr, 2);
    sr8 += __shfl_xor_sync(FULL, sr8, 1); sr8 += __shfl_xor_sync(FULL, sr8, 2);
    dr  += __shfl_xor_sync(FULL, dr, 1);  dr  += __shfl_xor_sync(FULL, dr, 2);
    dr8 += __shfl_xor_sync(FULL, dr8, 1); dr8 += __shfl_xor_sync(FULL, dr8, 2);
    if (ct == 0) {
        asrc[(row0 + gr) * 4 + w] = sr;
        asrc[(row0 + gr + 8) * 4 + w] = sr8;
        adst[(row0 + gr) * 4 + w] = dr;
        adst[(row0 + gr + 8) * 4 + w] = dr8;
    }
}

// ---------------- layer 1 aggregation: HFMA2 fp16 accum -> x1 fp16 ---------
__global__ void k_agg1(const int* __restrict__ off, const int* __restrict__ csr,
                       const __half* __restrict__ hfeat, const float* __restrict__ asrc,
                       const float* __restrict__ adst, const float* __restrict__ bias,
                       __half* __restrict__ x1out) {
    __shared__ int   sm_s[8][32];
    __shared__ uint4 sm_w[8][32];     // per-edge scaled half2-splat weights (4 heads)
    int wid = threadIdx.x >> 5;
    int lane = threadIdx.x & 31;
    int d = blockIdx.x * 8 + wid;
    if (d >= NN) return;
    int b0 = off[d], b1 = off[d + 1];

    float4 adv = ((const float4*)adst)[d];
    int hh = lane >> 3;

    float s0 = 0.f, s1 = 0.f, s2 = 0.f, s3 = 0.f;
    unsigned int aA0 = 0, aA1 = 0, aA2 = 0, aA3 = 0;   // even-edge fp16x2 accums
    unsigned int aB0 = 0, aB1 = 0, aB2 = 0, aB3 = 0;   // odd-edge fp16x2 accums

    const uint4* hf = (const uint4*)hfeat;
    const float4* as4 = (const float4*)asrc;
    const unsigned int* wqp = (const unsigned int*)&sm_w[wid][0];

    for (int base = b0; base < b1; base += 32) {
        int k = base + lane;
        int sidx = 0;
        uint4 wq = make_uint4(0, 0, 0, 0);
        if (k < b1) {
            sidx = csr[k];
            float4 a = as4[sidx];
            float w0 = __expf(lrelu(a.x + adv.x));
            float w1 = __expf(lrelu(a.y + adv.y));
            float w2 = __expf(lrelu(a.z + adv.z));
            float w3 = __expf(lrelu(a.w + adv.w));
            s0 += w0; s1 += w1; s2 += w2; s3 += w3;
            wq.x = splath2(w0 * WSCALE);
            wq.y = splath2(w1 * WSCALE);
            wq.z = splath2(w2 * WSCALE);
            wq.w = splath2(w3 * WSCALE);
        }
        sm_s[wid][lane] = sidx;
        sm_w[wid][lane] = wq;
        __syncwarp();
        int cnt = min(32, b1 - base);
        int e = 0;
        for (; e + 2 <= cnt; e += 2) {
            int ss0 = sm_s[wid][e];
            int ss1 = sm_s[wid][e + 1];
            unsigned int w0 = wqp[e * 4 + hh];
            unsigned int w1 = wqp[(e + 1) * 4 + hh];
            uint4 v0 = hf[ss0 * 32 + lane];
            uint4 v1 = hf[ss1 * 32 + lane];
            HFMA2(aA0, w0, v0.x); HFMA2(aA1, w0, v0.y);
            HFMA2(aA2, w0, v0.z); HFMA2(aA3, w0, v0.w);
            HFMA2(aB0, w1, v1.x); HFMA2(aB1, w1, v1.y);
            HFMA2(aB2, w1, v1.z); HFMA2(aB3, w1, v1.w);
        }
        if (e < cnt) {
            int ss0 = sm_s[wid][e];
            unsigned int w0 = wqp[e * 4 + hh];
            uint4 v0 = hf[ss0 * 32 + lane];
            HFMA2(aA0, w0, v0.x); HFMA2(aA1, w0, v0.y);
            HFMA2(aA2, w0, v0.z); HFMA2(aA3, w0, v0.w);
        }
        __syncwarp();
    }

    s0 = warp_sum(s0); s1 = warp_sum(s1); s2 = warp_sum(s2); s3 = warp_sum(s3);
    float iH = (hh == 0) ? 1.f / (s0 + 1e-16f)
             : (hh == 1) ? 1.f / (s1 + 1e-16f)
             : (hh == 2) ? 1.f / (s2 + 1e-16f)
             :             1.f / (s3 + 1e-16f);
    float sc = iH * WUNSCALE;

    float acc[8];
    {
        float2 pa, pb;
        pa = h2f2(aA0); pb = h2f2(aB0); acc[0] = (pa.x + pb.x) * sc; acc[1] = (pa.y + pb.y) * sc;
        pa = h2f2(aA1); pb = h2f2(aB1); acc[2] = (pa.x + pb.x) * sc; acc[3] = (pa.y + pb.y) * sc;
        pa = h2f2(aA2); pb = h2f2(aB2); acc[4] = (pa.x + pb.x) * sc; acc[5] = (pa.y + pb.y) * sc;
        pa = h2f2(aA3); pb = h2f2(aB3); acc[6] = (pa.x + pb.x) * sc; acc[7] = (pa.y + pb.y) * sc;
    }

#pragma unroll
    for (int j = 0; j < 8; j++) {
        acc[j] += __shfl_xor_sync(FULL, acc[j], 8);
        acc[j] += __shfl_xor_sync(FULL, acc[j], 16);
    }
    if (lane < 8) {
        float4 bb0 = ((const float4*)bias)[lane * 2];
        float4 bb1 = ((const float4*)bias)[lane * 2 + 1];
        uint4 pk;
        pk.x = packh2(fmaxf(acc[0] * 0.25f + bb0.x, 0.f), fmaxf(acc[1] * 0.25f + bb0.y, 0.f));
        pk.y = packh2(fmaxf(acc[2] * 0.25f + bb0.z, 0.f), fmaxf(acc[3] * 0.25f + bb0.w, 0.f));
        pk.z = packh2(fmaxf(acc[4] * 0.25f + bb1.x, 0.f), fmaxf(acc[5] * 0.25f + bb1.y, 0.f));
        pk.w = packh2(fmaxf(acc[6] * 0.25f + bb1.z, 0.f), fmaxf(acc[7] * 0.25f + bb1.w, 0.f));
        ((uint4*)x1out)[d * 8 + lane] = pk;
    }
}

// ---------------- GEMM2: 128 nodes/block, 4-node W amortization ------------
__global__ void __launch_bounds__(256) k_gemm2(
        const __half* __restrict__ x1, const float* __restrict__ W2,
        const float* __restrict__ as2, const float* __restrict__ ad2,
        __half* __restrict__ h2out, float* __restrict__ asrc2,
        float* __restrict__ adst2) {
    __shared__ float  smW[64 * 64];
    __shared__ __half smX[128 * 68];
    int t = threadIdx.x;
    int n0 = blockIdx.x * 128;

#pragma unroll
    for (int i = 0; i < 4; i++)
        ((float4*)smW)[t + 256 * i] = ((const float4*)W2)[t + 256 * i];
    {
        int row = t >> 1, part = t & 1;
        int n = n0 + row;
        const uint4* gsrc = (const uint4*)x1 + (long long)n * 8 + part * 4;
        uint2* drow = (uint2*)(smX + row * 68 + part * 32);
#pragma unroll
        for (int i = 0; i < 4; i++) {
            uint4 v = (n < NN) ? gsrc[i] : make_uint4(0, 0, 0, 0);
            drow[2 * i]     = make_uint2(v.x, v.y);
            drow[2 * i + 1] = make_uint2(v.z, v.w);
        }
    }
    __syncthreads();

    int grp = t >> 3;
    int cg  = t & 7;
    int nl0 = grp * 4;

    unsigned long long acc[4][4];
#pragma unroll
    for (int r = 0; r < 4; r++)
#pragma unroll
        for (int j = 0; j < 4; j++) acc[r][j] = 0ull;

    const ulonglong2* Wr = (const ulonglong2*)smW;
#pragma unroll 4
    for (int k = 0; k < 64; k++) {
        ulonglong2 w0 = Wr[k * 16 + cg * 2];
        ulonglong2 w1 = Wr[k * 16 + cg * 2 + 1];
#pragma unroll
        for (int r = 0; r < 4; r++) {
            float xv = __half2float(smX[(nl0 + r) * 68 + k]);
            unsigned long long xs; SPLAT2(xs, xv);
            FMA2(acc[r][0], xs, w0.x); FMA2(acc[r][1], xs, w0.y);
            FMA2(acc[r][2], xs, w1.x); FMA2(acc[r][3], xs, w1.y);
        }
    }

    int hd = cg >> 2;
    const float4* a4 = (const float4*)(as2 + hd * 32 + (cg & 3) * 8);
    const float4* d4v = (const float4*)(ad2 + hd * 32 + (cg & 3) * 8);
    float4 aa0 = a4[0], aa1 = a4[1];
    float4 dd0 = d4v[0], dd1 = d4v[1];

#pragma unroll
    for (int r = 0; r < 4; r++) {
        int d = n0 + nl0 + r;
        float c[8];
        unsigned int lo, hi;
        UNPACK2(lo, hi, acc[r][0]); c[0] = __uint_as_float(lo); c[1] = __uint_as_float(hi);
        UNPACK2(lo, hi, acc[r][1]); c[2] = __uint_as_float(lo); c[3] = __uint_as_float(hi);
        UNPACK2(lo, hi, acc[r][2]); c[4] = __uint_as_float(lo); c[5] = __uint_as_float(hi);
        UNPACK2(lo, hi, acc[r][3]); c[6] = __uint_as_float(lo); c[7] = __uint_as_float(hi);
        float ps = c[0]*aa0.x + c[1]*aa0.y + c[2]*aa0.z + c[3]*aa0.w
                 + c[4]*aa1.x + c[5]*aa1.y + c[6]*aa1.z + c[7]*aa1.w;
        float pd = c[0]*dd0.x + c[1]*dd0.y + c[2]*dd0.z + c[3]*dd0.w
                 + c[4]*dd1.x + c[5]*dd1.y + c[6]*dd1.z + c[7]*dd1.w;
        ps += __shfl_xor_sync(FULL, ps, 1);
        ps += __shfl_xor_sync(FULL, ps, 2);
        pd += __shfl_xor_sync(FULL, pd, 1);
        pd += __shfl_xor_sync(FULL, pd, 2);
        if (d < NN) {
            uint4 pk;
            pk.x = packh2(c[0], c[1]);
            pk.y = packh2(c[2], c[3]);
            pk.z = packh2(c[4], c[5]);
            pk.w = packh2(c[6], c[7]);
            ((uint4*)h2out)[d * 8 + cg] = pk;
            if ((cg & 3) == 0) {
                asrc2[d * 2 + hd] = ps;
                adst2[d * 2 + hd] = pd;
            }
        }
    }
}

// ---------------- layer 2 aggregation (HFMA2) + pool + fused heads ---------
__global__ void k_agg2(const int* __restrict__ off, const int* __restrict__ csr,
                       const __half* __restrict__ hfeat, const float* __restrict__ asrc,
                       const float* __restrict__ adst, const float* __restrict__ bias,
                       const int* __restrict__ batch, float* __restrict__ sums,
                       float* __restrict__ gcnt,
                       const float* __restrict__ cW1, const float* __restrict__ cb1,
                       const float* __restrict__ cW2, const float* __restrict__ cb2,
                       const float* __restrict__ hW1, const float* __restrict__ hb1,
                       const float* __restrict__ hW2, const float* __restrict__ hb2,
                       float* __restrict__ out, int* __restrict__ cntz,
                       int* __restrict__ done) {
    __shared__ int   sm_s[8][32];
    __shared__ uint2 sm_w[8][32];     // per-edge scaled half2-splat weights (2 heads)
    __shared__ int sm_last;
    int wid = threadIdx.x >> 5;
    int lane = threadIdx.x & 31;
    int d = blockIdx.x * 8 + wid;

    if (d < NN) {
        int b0 = off[d], b1 = off[d + 1];
        float2 adv = ((const float2*)adst)[d];
        int hh = lane >> 4;
        float s0 = 0.f, s1 = 0.f;
        unsigned int accA = 0, accB = 0;
        const unsigned int* hf = (const unsigned int*)hfeat;
        const float2* as2p = (const float2*)asrc;
        const unsigned int* whp = (const unsigned int*)&sm_w[wid][0];

        for (int base = b0; base < b1; base += 32) {
            int k = base + lane;
            int sidx = 0;
            uint2 wq = make_uint2(0, 0);
            if (k < b1) {
                sidx = csr[k];
                float2 a = as2p[sidx];
                float w0 = __expf(lrelu(a.x + adv.x));
                float w1 = __expf(lrelu(a.y + adv.y));
                s0 += w0; s1 += w1;
                wq.x = splath2(w0 * WSCALE);
                wq.y = splath2(w1 * WSCALE);
            }
            sm_s[wid][lane] = sidx;
            sm_w[wid][lane] = wq;
            __syncwarp();
            int cnt = min(32, b1 - base);
            int e = 0;
            for (; e + 2 <= cnt; e += 2) {
                int ss0 = sm_s[wid][e];
                int ss1 = sm_s[wid][e + 1];
                unsigned int w0 = whp[e * 2 + hh];
                unsigned int w1 = whp[(e + 1) * 2 + hh];
                unsigned int v0 = hf[ss0 * 32 + lane];
                unsigned int v1 = hf[ss1 * 32 + lane];
                HFMA2(accA, w0, v0);
                HFMA2(accB, w1, v1);
            }
            if (e < cnt) {
                int ss0 = sm_s[wid][e];
                unsigned int w0 = whp[e * 2 + hh];
                unsigned int v0 = hf[ss0 * 32 + lane];
                HFMA2(accA, w0, v0);
            }
            __syncwarp();
        }

        s0 = warp_sum(s0); s1 = warp_sum(s1);
        float iH = hh ? 1.f / (s1 + 1e-16f) : 1.f / (s0 + 1e-16f);
        float scl = iH * WUNSCALE;
        float2 pa = h2f2(accA), pb = h2f2(accB);
        float ax = (pa.x + pb.x) * scl;
        float ay = (pa.y + pb.y) * scl;
        ax += __shfl_xor_sync(FULL, ax, 16);
        ay += __shfl_xor_sync(FULL, ay, 16);
        if (lane < 16) {
            const float2 b = ((const float2*)bias)[lane];
            float ox = fmaxf(ax * 0.5f + b.x, 0.f);
            float oy = fmaxf(ay * 0.5f + b.y, 0.f);
            int g = batch[d];
            atomicAdd(&sums[g * 32 + 2 * lane], ox);
            atomicAdd(&sums[g * 32 + 2 * lane + 1], oy);
            if (lane == 0) atomicAdd(&gcnt[g], 1.f);
        }
    }

    __threadfence();
    __syncthreads();
    if (threadIdx.x == 0)
        sm_last = (atomicAdd(done, 1) == gridDim.x - 1) ? 1 : 0;
    __syncthreads();
    if (!sm_last) return;

    int t = threadIdx.x;
    int4 z = make_int4(0, 0, 0, 0);
    for (int i = t; i < NN / 4; i += 256) ((int4*)cntz)[i] = z;
    if (t == 0) *done = 0;

    if (t < GG) {
        int g = t;
        float emb[32];
        float c_ = __ldcg(&gcnt[g]);
        c_ = (c_ > 1.f) ? c_ : 1.f;
        for (int c = 0; c < 32; c++) emb[c] = __ldcg(&sums[g * 32 + c]) / c_;
        float oh = hb2[0], oc = cb2[0];
        for (int j = 0; j < 16; j++) {
            float sh = hb1[j], sc = cb1[j];
            for (int c = 0; c < 32; c++) {
                sh = fmaf(emb[c], hW1[c * 16 + j], sh);
                sc = fmaf(emb[c], cW1[c * 16 + j], sc);
            }
            sh = fmaxf(sh, 0.f);
            sc = fmaxf(sc, 0.f);
            oh = fmaf(sh, hW2[j], oh);
            oc = fmaf(sc, cW2[j], oc);
        }
        out[g]      = 1.f / (1.f + __expf(-oh));
        out[GG + g] = 1.f / (1.f + __expf(-oc));
    }
}

// ---------------- host ----------------
static inline int cdiv(long long a, int b) { return (int)((a + b - 1) / b); }

extern "C" void kernel_launch(void* const* d_in, const int* in_sizes, int n_in,
                              void* d_out, int out_size) {
    const float* x     = (const float*)d_in[0];
    const int*   ei    = (const int*)  d_in[1];
    const int*   batch = (const int*)  d_in[2];
    const float* W1  = (const float*)d_in[3];
    const float* as1 = (const float*)d_in[4];
    const float* ad1 = (const float*)d_in[5];
    const float* b1  = (const float*)d_in[6];
    const float* W2  = (const float*)d_in[7];
    const float* as2 = (const float*)d_in[8];
    const float* ad2 = (const float*)d_in[9];
    const float* b2  = (const float*)d_in[10];
    const float* cW1 = (const float*)d_in[11];
    const float* cb1 = (const float*)d_in[12];
    const float* cW2 = (const float*)d_in[13];
    const float* cb2 = (const float*)d_in[14];
    const float* hW1 = (const float*)d_in[15];
    const float* hb1 = (const float*)d_in[16];
    const float* hW2 = (const float*)d_in[17];
    const float* hb2 = (const float*)d_in[18];

    const int* src = ei;
    const int* dst = ei + EE;

    __half *p_h, *p_x1, *p_h2;
    float *p_asrc, *p_adst, *p_asrc2, *p_adst2, *p_sums, *p_gcnt;
    int *p_cnt, *p_off, *p_cur, *p_csr, *p_done;
    cudaGetSymbolAddress((void**)&p_h, g_h);
    cudaGetSymbolAddress((void**)&p_x1, g_x1);
    cudaGetSymbolAddress((void**)&p_h2, g_h2);
    cudaGetSymbolAddress((void**)&p_asrc, g_asrc);
    cudaGetSymbolAddress((void**)&p_adst, g_adst);
    cudaGetSymbolAddress((void**)&p_asrc2, g_asrc2);
    cudaGetSymbolAddress((void**)&p_adst2, g_adst2);
    cudaGetSymbolAddress((void**)&p_cnt, g_cnt);
    cudaGetSymbolAddress((void**)&p_off, g_off);
    cudaGetSymbolAddress((void**)&p_cur, g_cur);
    cudaGetSymbolAddress((void**)&p_csr, g_csr);
    cudaGetSymbolAddress((void**)&p_sums, g_sums);
    cudaGetSymbolAddress((void**)&p_gcnt, g_gcnt);
    cudaGetSymbolAddress((void**)&p_done, g_done);

    const int T = 256;

    k_prep<<<APACK_BLOCKS + BPACK_BLOCKS + COUNT_BLOCKS, T>>>(x, W1, dst, p_cnt);
    k_scan<<<1, 1024>>>(p_cnt, p_off, p_cur, p_sums, p_gcnt);
    k_mma_build<<<MMA_BLOCKS + BUILD_BLOCKS, T>>>(as1, ad1, p_h, p_asrc, p_adst,
                                                  src, dst, p_cur, p_csr);
    k_agg1<<<AGG_BLOCKS, T>>>(p_off, p_csr, p_h, p_asrc, p_adst, b1, p_x1);
    k_gemm2<<<cdiv(NN, 128), T>>>(p_x1, W2, as2, ad2, p_h2, p_asrc2, p_adst2);
    k_agg2<<<AGG_BLOCKS, T>>>(p_off, p_csr, p_h2, p_asrc2, p_adst2, b2,
                              batch, p_sums, p_gcnt,
                              cW1, cb1, cW2, cb2, hW1, hb1, hW2, hb2,
                              (float*)d_out, p_cnt, p_done);
}

// round 16
// speedup vs baseline: 1.2586x; 1.0435x over previous
#include <cuda_runtime.h>
#include <cuda_fp16.h>
#include <math.h>

#define NN 20000
#define EE 320000
#define ET (EE + NN)
#define GG 64
#define FULL 0xffffffffu

#define MT (NN / 16)
#define APACK_BLOCKS MT
#define BPACK_BLOCKS 32
#define COUNT_BLOCKS ((EE / 4 + 255) / 256)
#define MMA_BLOCKS ((MT * 4 + 7) / 8)
#define BUILD_BLOCKS ((EE / 4 + NN + 255) / 256)
#define AGG_BLOCKS ((NN + 7) / 8)

// ---------------- scratch ----------------
__device__ __half g_h[NN * 256];
__device__ __half g_x1[NN * 64];
__device__ __half g_h2[NN * 64];
__device__ uint4  g_ap[MT * 8 * 32];
__device__ uint2  g_w1p[8 * 32 * 32];
__device__ float g_asrc[NN * 4];
__device__ float g_adst[NN * 4];
__device__ float g_asrc2[NN * 2];
__device__ float g_adst2[NN * 2];
__device__ int   g_cnt[NN];
__device__ int   g_off[NN + 1];
__device__ int   g_cur[NN];
__device__ int   g_csr[ET];
__device__ float g_sums[GG * 32];
__device__ float g_gcnt[GG];
__device__ int   g_done;

__device__ __forceinline__ float lrelu(float v) { return v > 0.f ? v : 0.2f * v; }
__device__ __forceinline__ float warp_sum(float v) {
#pragma unroll
    for (int o = 16; o > 0; o >>= 1) v += __shfl_xor_sync(FULL, v, o);
    return v;
}
__device__ __forceinline__ unsigned int packh2(float a, float b) {
    half2 h = __floats2half2_rn(a, b);
    return *(unsigned int*)&h;
}
__device__ __forceinline__ void mma16816(float& c0, float& c1, float& c2, float& c3,
                                         unsigned int a0, unsigned int a1,
                                         unsigned int a2, unsigned int a3,
                                         unsigned int b0, unsigned int b1) {
    asm volatile(
        "mma.sync.aligned.m16n8k16.row.col.f32.f16.f16.f32 "
        "{%0,%1,%2,%3}, {%4,%5,%6,%7}, {%8,%9}, {%0,%1,%2,%3};"
        : "+f"(c0), "+f"(c1), "+f"(c2), "+f"(c3)
        : "r"(a0), "r"(a1), "r"(a2), "r"(a3), "r"(b0), "r"(b1));
}

#define SPLAT2(out, f) asm("mov.b64 %0, {%1, %1};" : "=l"(out) : "r"(__float_as_uint(f)))
#define FMA2(acc, a, b) asm("fma.rn.f32x2 %0, %1, %2, %0;" : "+l"(acc) : "l"(a), "l"(b))
#define UNPACK2(lo, hi, in) asm("mov.b64 {%0, %1}, %2;" : "=r"(lo), "=r"(hi) : "l"(in))

// ---------------- prep: pack A frags, pack B frags, degree count ----------
__global__ void k_prep(const float* __restrict__ x, const float* __restrict__ W1,
                       const int* __restrict__ dst, int* __restrict__ cnt) {
    int b = blockIdx.x, t = threadIdx.x;
    if (b < APACK_BLOCKS) {
        int gid = b * 256 + t;
        int lane = gid & 31;
        int ks = (gid >> 5) & 7;
        int mt = gid >> 8;
        int gr = lane >> 2, ct = lane & 3;
        int r0 = mt * 16 + gr;
        const float2* x2 = (const float2*)x;
        float2 p00 = x2[r0 * 64 + ks * 8 + ct];
        float2 p01 = x2[r0 * 64 + ks * 8 + ct + 4];
        float2 p10 = x2[(r0 + 8) * 64 + ks * 8 + ct];
        float2 p11 = x2[(r0 + 8) * 64 + ks * 8 + ct + 4];
        uint4 frag;
        frag.x = packh2(p00.x, p00.y);
        frag.y = packh2(p10.x, p10.y);
        frag.z = packh2(p01.x, p01.y);
        frag.w = packh2(p11.x, p11.y);
        g_ap[(mt * 8 + ks) * 32 + lane] = frag;
    } else if (b < APACK_BLOCKS + BPACK_BLOCKS) {
        int gid = (b - APACK_BLOCKS) * 256 + t;
        int lane = gid & 31;
        int ntg = (gid >> 5) & 31;
        int ks = gid >> 10;
        int gr = lane >> 2, ct = lane & 3;
        int col = ntg * 8 + gr;
        int k0 = ks * 16 + 2 * ct;
        uint2 frag;
        frag.x = packh2(W1[k0 * 256 + col],       W1[(k0 + 1) * 256 + col]);
        frag.y = packh2(W1[(k0 + 8) * 256 + col], W1[(k0 + 9) * 256 + col]);
        g_w1p[(ks * 32 + ntg) * 32 + lane] = frag;
    } else {
        int gid = (b - APACK_BLOCKS - BPACK_BLOCKS) * 256 + t;
        if (gid < EE / 4) {
            int4 d4 = ((const int4*)dst)[gid];
            atomicAdd(&cnt[d4.x], 1);
            atomicAdd(&cnt[d4.y], 1);
            atomicAdd(&cnt[d4.z], 1);
            atomicAdd(&cnt[d4.w], 1);
        }
    }
}

// ---------------- scan (+1 self-loop; zero pooling buffers) ----------------
__global__ void k_scan(const int* __restrict__ cnt, int* __restrict__ off,
                       int* __restrict__ cur, float* __restrict__ sums,
                       float* __restrict__ gcnt) {
    __shared__ int ssum[1024];
    const int CH = 20;
    int t = threadIdx.x;
    sums[t] = 0.f; sums[t + 1024] = 0.f;
    if (t < GG) gcnt[t] = 0.f;
    int base = t * CH;
    int local[CH];
    int s = 0;
#pragma unroll
    for (int j = 0; j < CH; j++) {
        int v = (base + j < NN) ? (cnt[base + j] + 1) : 0;
        local[j] = s;
        s += v;
    }
    ssum[t] = s;
    __syncthreads();
    for (int o = 1; o < 1024; o <<= 1) {
        int v = (t >= o) ? ssum[t - o] : 0;
        __syncthreads();
        ssum[t] += v;
        __syncthreads();
    }
    int pre = ssum[t] - s;
#pragma unroll
    for (int j = 0; j < CH; j++) {
        if (base + j < NN) { off[base + j] = pre + local[j]; cur[base + j] = pre + local[j]; }
    }
    if (t == 1023) off[NN] = ssum[1023];
}

// ---------------- fused: tensor-core GEMM1 + att1  |  CSR build ------------
__global__ void __launch_bounds__(256) k_mma_build(
        const float* __restrict__ as1, const float* __restrict__ ad1,
        __half* __restrict__ h, float* __restrict__ asrc, float* __restrict__ adst,
        const int* __restrict__ src, const int* __restrict__ dst,
        int* __restrict__ cur, int* __restrict__ csr) {
    if (blockIdx.x >= MMA_BLOCKS) {
        int t = (blockIdx.x - MMA_BLOCKS) * 256 + threadIdx.x;
        if (t < EE / 4) {
            int4 s4 = ((const int4*)src)[t];
            int4 d4 = ((const int4*)dst)[t];
            csr[atomicAdd(&cur[d4.x], 1)] = s4.x;
            csr[atomicAdd(&cur[d4.y], 1)] = s4.y;
            csr[atomicAdd(&cur[d4.z], 1)] = s4.z;
            csr[atomicAdd(&cur[d4.w], 1)] = s4.w;
        } else {
            int n = t - EE / 4;
            if (n < NN) csr[atomicAdd(&cur[n], 1)] = n;
        }
        return;
    }

    int gw = blockIdx.x * 8 + (threadIdx.x >> 5);
    int lane = threadIdx.x & 31;
    int mt = gw >> 2;
    int w = gw & 3;
    if (mt >= MT) return;
    int gr = lane >> 2, ct = lane & 3;
    int row0 = mt * 16;

    uint4 a[8];
#pragma unroll
    for (int ks = 0; ks < 8; ks++) a[ks] = g_ap[(mt * 8 + ks) * 32 + lane];

    float sr = 0.f, sr8 = 0.f, dr = 0.f, dr8 = 0.f;
    half2* h2out = (half2*)h;

#pragma unroll
    for (int nt = 0; nt < 8; nt++) {
        int ntg = w * 8 + nt;
        float c0 = 0.f, c1 = 0.f, c2 = 0.f, c3 = 0.f;
#pragma unroll
        for (int ks = 0; ks < 8; ks++) {
            uint2 bfr = g_w1p[(ks * 32 + ntg) * 32 + lane];
            mma16816(c0, c1, c2, c3, a[ks].x, a[ks].y, a[ks].z, a[ks].w,
                     bfr.x, bfr.y);
        }
        h2out[(row0 + gr) * 128 + w * 32 + nt * 4 + ct]     = __floats2half2_rn(c0, c1);
        h2out[(row0 + gr + 8) * 128 + w * 32 + nt * 4 + ct] = __floats2half2_rn(c2, c3);
        float2 av = ((const float2*)as1)[w * 32 + nt * 4 + ct];
        float2 dv = ((const float2*)ad1)[w * 32 + nt * 4 + ct];
        sr  += c0 * av.x + c1 * av.y;
        sr8 += c2 * av.x + c3 * av.y;
        dr  += c0 * dv.x + c1 * dv.y;
        dr8 += c2 * dv.x + c3 * dv.y;
    }
    sr  += __shfl_xor_sync(FULL, sr, 1);  sr  += __shfl_xor_sync(FULL, sr, 2);
    sr8 += __shfl_xor_sync(FULL, sr8, 1); sr8 += __shfl_xor_sync(FULL, sr8, 2);
    dr  += __shfl_xor_sync(FULL, dr, 1);  dr  += __shfl_xor_sync(FULL, dr, 2);
    dr8 += __shfl_xor_sync(FULL, dr8, 1); dr8 += __shfl_xor_sync(FULL, dr8, 2);
    if (ct == 0) {
        asrc[(row0 + gr) * 4 + w] = sr;
        asrc[(row0 + gr + 8) * 4 + w] = sr8;
        adst[(row0 + gr) * 4 + w] = dr;
        adst[(row0 + gr + 8) * 4 + w] = dr8;
    }
}

// ---------------- layer 1 aggregation -> x1 fp16 (high occupancy) ----------
__global__ void __launch_bounds__(256, 6) k_agg1(
        const int* __restrict__ off, const int* __restrict__ csr,
        const __half* __restrict__ hfeat, const float* __restrict__ asrc,
        const float* __restrict__ adst, const float* __restrict__ bias,
        __half* __restrict__ x1out) {
    __shared__ int    sm_s[8][32];
    __shared__ float4 sm_w[8][32];
    int wid = threadIdx.x >> 5;
    int lane = threadIdx.x & 31;
    int d = blockIdx.x * 8 + wid;
    if (d >= NN) return;
    int b0 = off[d], b1 = off[d + 1];

    float4 adv = ((const float4*)adst)[d];
    int hh = lane >> 3;

    float s0 = 0.f, s1 = 0.f, s2 = 0.f, s3 = 0.f;
    float acc[8];
#pragma unroll
    for (int j = 0; j < 8; j++) acc[j] = 0.f;

    const uint4* hf = (const uint4*)hfeat;
    const float4* as4 = (const float4*)asrc;
    const float* wp = (const float*)&sm_w[wid][0];

    for (int base = b0; base < b1; base += 32) {
        int k = base + lane;
        float4 w = make_float4(0.f, 0.f, 0.f, 0.f);
        int sidx = 0;
        if (k < b1) {
            sidx = csr[k];
            float4 a = as4[sidx];
            w.x = __expf(lrelu(a.x + adv.x));
            w.y = __expf(lrelu(a.y + adv.y));
            w.z = __expf(lrelu(a.z + adv.z));
            w.w = __expf(lrelu(a.w + adv.w));
            s0 += w.x; s1 += w.y; s2 += w.z; s3 += w.w;
        }
        sm_s[wid][lane] = sidx;
        sm_w[wid][lane] = w;
        __syncwarp();
        int cnt = min(32, b1 - base);
        for (int e = 0; e < cnt; e++) {
            int ss = sm_s[wid][e];
            float we = wp[e * 4 + hh];
            uint4 v = hf[ss * 32 + lane];
            float2 p;
            p = __half22float2(*(half2*)&v.x); acc[0] = fmaf(we, p.x, acc[0]); acc[1] = fmaf(we, p.y, acc[1]);
            p = __half22float2(*(half2*)&v.y); acc[2] = fmaf(we, p.x, acc[2]); acc[3] = fmaf(we, p.y, acc[3]);
            p = __half22float2(*(half2*)&v.z); acc[4] = fmaf(we, p.x, acc[4]); acc[5] = fmaf(we, p.y, acc[5]);
            p = __half22float2(*(half2*)&v.w); acc[6] = fmaf(we, p.x, acc[6]); acc[7] = fmaf(we, p.y, acc[7]);
        }
        __syncwarp();
    }

    s0 = warp_sum(s0); s1 = warp_sum(s1); s2 = warp_sum(s2); s3 = warp_sum(s3);
    float iH = (hh == 0) ? 1.f / (s0 + 1e-16f)
             : (hh == 1) ? 1.f / (s1 + 1e-16f)
             : (hh == 2) ? 1.f / (s2 + 1e-16f)
             :             1.f / (s3 + 1e-16f);
#pragma unroll
    for (int j = 0; j < 8; j++) acc[j] *= iH;

#pragma unroll
    for (int j = 0; j < 8; j++) {
        acc[j] += __shfl_xor_sync(FULL, acc[j], 8);
        acc[j] += __shfl_xor_sync(FULL, acc[j], 16);
    }
    if (lane < 8) {
        float4 bb0 = ((const float4*)bias)[lane * 2];
        float4 bb1 = ((const float4*)bias)[lane * 2 + 1];
        uint4 pk;
        pk.x = packh2(fmaxf(acc[0] * 0.25f + bb0.x, 0.f), fmaxf(acc[1] * 0.25f + bb0.y, 0.f));
        pk.y = packh2(fmaxf(acc[2] * 0.25f + bb0.z, 0.f), fmaxf(acc[3] * 0.25f + bb0.w, 0.f));
        pk.z = packh2(fmaxf(acc[4] * 0.25f + bb1.x, 0.f), fmaxf(acc[5] * 0.25f + bb1.y, 0.f));
        pk.w = packh2(fmaxf(acc[6] * 0.25f + bb1.z, 0.f), fmaxf(acc[7] * 0.25f + bb1.w, 0.f));
        ((uint4*)x1out)[d * 8 + lane] = pk;
    }
}

// ---------------- GEMM2: 128 nodes/block, 4-node W amortization ------------
__global__ void __launch_bounds__(256) k_gemm2(
        const __half* __restrict__ x1, const float* __restrict__ W2,
        const float* __restrict__ as2, const float* __restrict__ ad2,
        __half* __restrict__ h2out, float* __restrict__ asrc2,
        float* __restrict__ adst2) {
    __shared__ float  smW[64 * 64];
    __shared__ __half smX[128 * 68];
    int t = threadIdx.x;
    int n0 = blockIdx.x * 128;

#pragma unroll
    for (int i = 0; i < 4; i++)
        ((float4*)smW)[t + 256 * i] = ((const float4*)W2)[t + 256 * i];
    {
        int row = t >> 1, part = t & 1;
        int n = n0 + row;
        const uint4* gsrc = (const uint4*)x1 + (long long)n * 8 + part * 4;
        uint2* drow = (uint2*)(smX + row * 68 + part * 32);
#pragma unroll
        for (int i = 0; i < 4; i++) {
            uint4 v = (n < NN) ? gsrc[i] : make_uint4(0, 0, 0, 0);
            drow[2 * i]     = make_uint2(v.x, v.y);
            drow[2 * i + 1] = make_uint2(v.z, v.w);
        }
    }
    __syncthreads();

    int grp = t >> 3;
    int cg  = t & 7;
    int nl0 = grp * 4;

    unsigned long long acc[4][4];
#pragma unroll
    for (int r = 0; r < 4; r++)
#pragma unroll
        for (int j = 0; j < 4; j++) acc[r][j] = 0ull;

    const ulonglong2* Wr = (const ulonglong2*)smW;
#pragma unroll 4
    for (int k = 0; k < 64; k++) {
        ulonglong2 w0 = Wr[k * 16 + cg * 2];
        ulonglong2 w1 = Wr[k * 16 + cg * 2 + 1];
#pragma unroll
        for (int r = 0; r < 4; r++) {
            float xv = __half2float(smX[(nl0 + r) * 68 + k]);
            unsigned long long xs; SPLAT2(xs, xv);
            FMA2(acc[r][0], xs, w0.x); FMA2(acc[r][1], xs, w0.y);
            FMA2(acc[r][2], xs, w1.x); FMA2(acc[r][3], xs, w1.y);
        }
    }

    int hd = cg >> 2;
    const float4* a4 = (const float4*)(as2 + hd * 32 + (cg & 3) * 8);
    const float4* d4v = (const float4*)(ad2 + hd * 32 + (cg & 3) * 8);
    float4 aa0 = a4[0], aa1 = a4[1];
    float4 dd0 = d4v[0], dd1 = d4v[1];

#pragma unroll
    for (int r = 0; r < 4; r++) {
        int d = n0 + nl0 + r;
        float c[8];
        unsigned int lo, hi;
        UNPACK2(lo, hi, acc[r][0]); c[0] = __uint_as_float(lo); c[1] = __uint_as_float(hi);
        UNPACK2(lo, hi, acc[r][1]); c[2] = __uint_as_float(lo); c[3] = __uint_as_float(hi);
        UNPACK2(lo, hi, acc[r][2]); c[4] = __uint_as_float(lo); c[5] = __uint_as_float(hi);
        UNPACK2(lo, hi, acc[r][3]); c[6] = __uint_as_float(lo); c[7] = __uint_as_float(hi);
        float ps = c[0]*aa0.x + c[1]*aa0.y + c[2]*aa0.z + c[3]*aa0.w
                 + c[4]*aa1.x + c[5]*aa1.y + c[6]*aa1.z + c[7]*aa1.w;
        float pd = c[0]*dd0.x + c[1]*dd0.y + c[2]*dd0.z + c[3]*dd0.w
                 + c[4]*dd1.x + c[5]*dd1.y + c[6]*dd1.z + c[7]*dd1.w;
        ps += __shfl_xor_sync(FULL, ps, 1);
        ps += __shfl_xor_sync(FULL, ps, 2);
        pd += __shfl_xor_sync(FULL, pd, 1);
        pd += __shfl_xor_sync(FULL, pd, 2);
        if (d < NN) {
            uint4 pk;
            pk.x = packh2(c[0], c[1]);
            pk.y = packh2(c[2], c[3]);
            pk.z = packh2(c[4], c[5]);
            pk.w = packh2(c[6], c[7]);
            ((uint4*)h2out)[d * 8 + cg] = pk;
            if ((cg & 3) == 0) {
                asrc2[d * 2 + hd] = ps;
                adst2[d * 2 + hd] = pd;
            }
        }
    }
}

// ---------------- layer 2 aggregation + pool + fused heads -----------------
__global__ void __launch_bounds__(256, 6) k_agg2(
        const int* __restrict__ off, const int* __restrict__ csr,
        const __half* __restrict__ hfeat, const float* __restrict__ asrc,
        const float* __restrict__ adst, const float* __restrict__ bias,
        const int* __restrict__ batch, float* __restrict__ sums,
        float* __restrict__ gcnt,
        const float* __restrict__ cW1, const float* __restrict__ cb1,
        const float* __restrict__ cW2, const float* __restrict__ cb2,
        const float* __restrict__ hW1, const float* __restrict__ hb1,
        const float* __restrict__ hW2, const float* __restrict__ hb2,
        float* __restrict__ out, int* __restrict__ cntz,
        int* __restrict__ done) {
    __shared__ int    sm_s[8][32];
    __shared__ float2 sm_w[8][32];
    __shared__ int sm_last;
    int wid = threadIdx.x >> 5;
    int lane = threadIdx.x & 31;
    int d = blockIdx.x * 8 + wid;

    if (d < NN) {
        int b0 = off[d], b1 = off[d + 1];
        float2 adv = ((const float2*)adst)[d];
        int hh = lane >> 4;
        float s0 = 0.f, s1 = 0.f;
        float2 acc = make_float2(0.f, 0.f);
        const half2* hf = (const half2*)hfeat;
        const float2* as2p = (const float2*)asrc;
        const float* wp = (const float*)&sm_w[wid][0];

        for (int base = b0; base < b1; base += 32) {
            int k = base + lane;
            float2 w = make_float2(0.f, 0.f);
            int sidx = 0;
            if (k < b1) {
                sidx = csr[k];
                float2 a = as2p[sidx];
                w.x = __expf(lrelu(a.x + adv.x));
                w.y = __expf(lrelu(a.y + adv.y));
                s0 += w.x; s1 += w.y;
            }
            sm_s[wid][lane] = sidx;
            sm_w[wid][lane] = w;
            __syncwarp();
            int cnt = min(32, b1 - base);
            for (int e = 0; e < cnt; e++) {
                int ss = sm_s[wid][e];
                float we = wp[e * 2 + hh];
                float2 v = __half22float2(hf[ss * 32 + lane]);
                acc.x = fmaf(we, v.x, acc.x);
                acc.y = fmaf(we, v.y, acc.y);
            }
            __syncwarp();
        }

        s0 = warp_sum(s0); s1 = warp_sum(s1);
        float iH = hh ? 1.f / (s1 + 1e-16f) : 1.f / (s0 + 1e-16f);
        acc.x *= iH;
        acc.y *= iH;
        acc.x += __shfl_xor_sync(FULL, acc.x, 16);
        acc.y += __shfl_xor_sync(FULL, acc.y, 16);
        if (lane < 16) {
            const float2 b = ((const float2*)bias)[lane];
            float ox = fmaxf(acc.x * 0.5f + b.x, 0.f);
            float oy = fmaxf(acc.y * 0.5f + b.y, 0.f);
            int g = batch[d];
            atomicAdd(&sums[g * 32 + 2 * lane], ox);
            atomicAdd(&sums[g * 32 + 2 * lane + 1], oy);
            if (lane == 0) atomicAdd(&gcnt[g], 1.f);
        }
    }

    __threadfence();
    __syncthreads();
    if (threadIdx.x == 0)
        sm_last = (atomicAdd(done, 1) == gridDim.x - 1) ? 1 : 0;
    __syncthreads();
    if (!sm_last) return;

    int t = threadIdx.x;
    int4 z = make_int4(0, 0, 0, 0);
    for (int i = t; i < NN / 4; i += 256) ((int4*)cntz)[i] = z;
    if (t == 0) *done = 0;

    if (t < GG) {
        int g = t;
        float emb[32];
        float c_ = __ldcg(&gcnt[g]);
        c_ = (c_ > 1.f) ? c_ : 1.f;
        for (int c = 0; c < 32; c++) emb[c] = __ldcg(&sums[g * 32 + c]) / c_;
        float oh = hb2[0], oc = cb2[0];
        for (int j = 0; j < 16; j++) {
            float sh = hb1[j], sc = cb1[j];
            for (int c = 0; c < 32; c++) {
                sh = fmaf(emb[c], hW1[c * 16 + j], sh);
                sc = fmaf(emb[c], cW1[c * 16 + j], sc);
            }
            sh = fmaxf(sh, 0.f);
            sc = fmaxf(sc, 0.f);
            oh = fmaf(sh, hW2[j], oh);
            oc = fmaf(sc, cW2[j], oc);
        }
        out[g]      = 1.f / (1.f + __expf(-oh));
        out[GG + g] = 1.f / (1.f + __expf(-oc));
    }
}

// ---------------- host ----------------
static inline int cdiv(long long a, int b) { return (int)((a + b - 1) / b); }

extern "C" void kernel_launch(void* const* d_in, const int* in_sizes, int n_in,
                              void* d_out, int out_size) {
    const float* x     = (const float*)d_in[0];
    const int*   ei    = (const int*)  d_in[1];
    const int*   batch = (const int*)  d_in[2];
    const float* W1  = (const float*)d_in[3];
    const float* as1 = (const float*)d_in[4];
    const float* ad1 = (const float*)d_in[5];
    const float* b1  = (const float*)d_in[6];
    const float* W2  = (const float*)d_in[7];
    const float* as2 = (const float*)d_in[8];
    const float* ad2 = (const float*)d_in[9];
    const float* b2  = (const float*)d_in[10];
    const float* cW1 = (const float*)d_in[11];
    const float* cb1 = (const float*)d_in[12];
    const float* cW2 = (const float*)d_in[13];
    const float* cb2 = (const float*)d_in[14];
    const float* hW1 = (const float*)d_in[15];
    const float* hb1 = (const float*)d_in[16];
    const float* hW2 = (const float*)d_in[17];
    const float* hb2 = (const float*)d_in[18];

    const int* src = ei;
    const int* dst = ei + EE;

    __half *p_h, *p_x1, *p_h2;
    float *p_asrc, *p_adst, *p_asrc2, *p_adst2, *p_sums, *p_gcnt;
    int *p_cnt, *p_off, *p_cur, *p_csr, *p_done;
    cudaGetSymbolAddress((void**)&p_h, g_h);
    cudaGetSymbolAddress((void**)&p_x1, g_x1);
    cudaGetSymbolAddress((void**)&p_h2, g_h2);
    cudaGetSymbolAddress((void**)&p_asrc, g_asrc);
    cudaGetSymbolAddress((void**)&p_adst, g_adst);
    cudaGetSymbolAddress((void**)&p_asrc2, g_asrc2);
    cudaGetSymbolAddress((void**)&p_adst2, g_adst2);
    cudaGetSymbolAddress((void**)&p_cnt, g_cnt);
    cudaGetSymbolAddress((void**)&p_off, g_off);
    cudaGetSymbolAddress((void**)&p_cur, g_cur);
    cudaGetSymbolAddress((void**)&p_csr, g_csr);
    cudaGetSymbolAddress((void**)&p_sums, g_sums);
    cudaGetSymbolAddress((void**)&p_gcnt, g_gcnt);
    cudaGetSymbolAddress((void**)&p_done, g_done);

    const int T = 256;

    k_prep<<<APACK_BLOCKS + BPACK_BLOCKS + COUNT_BLOCKS, T>>>(x, W1, dst, p_cnt);
    k_scan<<<1, 1024>>>(p_cnt, p_off, p_cur, p_sums, p_gcnt);
    k_mma_build<<<MMA_BLOCKS + BUILD_BLOCKS, T>>>(as1, ad1, p_h, p_asrc, p_adst,
                                                  src, dst, p_cur, p_csr);
    k_agg1<<<AGG_BLOCKS, T>>>(p_off, p_csr, p_h, p_asrc, p_adst, b1, p_x1);
    k_gemm2<<<cdiv(NN, 128), T>>>(p_x1, W2, as2, ad2, p_h2, p_asrc2, p_adst2);
    k_agg2<<<AGG_BLOCKS, T>>>(p_off, p_csr, p_h2, p_asrc2, p_adst2, b2,
                              batch, p_sums, p_gcnt,
                              cW1, cb1, cW2, cb2, hW1, hb1, hW2, hb2,
                              (float*)d_out, p_cnt, p_done);
}

// round 17
// speedup vs baseline: 1.2733x; 1.0117x over previous
#include <cuda_runtime.h>
#include <cuda_fp16.h>
#include <math.h>

#define NN 20000
#define EE 320000
#define ET (EE + NN)
#define GG 64
#define FULL 0xffffffffu

#define MT (NN / 16)
#define BPACK_BLOCKS 32
#define COUNT_BLOCKS ((EE / 4 + 255) / 256)
#define MMA_BLOCKS (MT / 2)                  // 625: each block packs+computes 2 m-tiles
#define BUILD_BLOCKS ((EE / 4 + NN + 255) / 256)
#define AGG_BLOCKS ((NN + 7) / 8)

// ---------------- scratch ----------------
__device__ __half g_h[NN * 256];
__device__ __half g_x1[NN * 64];
__device__ __half g_h2[NN * 64];
__device__ uint2  g_w1p[8 * 32 * 32];
__device__ float g_asrc[NN * 4];
__device__ float g_adst[NN * 4];
__device__ float g_asrc2[NN * 2];
__device__ float g_adst2[NN * 2];
__device__ int   g_cnt[NN];
__device__ int   g_off[NN + 1];
__device__ int   g_cur[NN];
__device__ int   g_csr[ET];
__device__ float g_sums[GG * 32];
__device__ float g_gcnt[GG];
__device__ int   g_done;

__device__ __forceinline__ float lrelu(float v) { return v > 0.f ? v : 0.2f * v; }
__device__ __forceinline__ float warp_sum(float v) {
#pragma unroll
    for (int o = 16; o > 0; o >>= 1) v += __shfl_xor_sync(FULL, v, o);
    return v;
}
__device__ __forceinline__ unsigned int packh2(float a, float b) {
    half2 h = __floats2half2_rn(a, b);
    return *(unsigned int*)&h;
}
__device__ __forceinline__ void mma16816(float& c0, float& c1, float& c2, float& c3,
                                         unsigned int a0, unsigned int a1,
                                         unsigned int a2, unsigned int a3,
                                         unsigned int b0, unsigned int b1) {
    asm volatile(
        "mma.sync.aligned.m16n8k16.row.col.f32.f16.f16.f32 "
        "{%0,%1,%2,%3}, {%4,%5,%6,%7}, {%8,%9}, {%0,%1,%2,%3};"
        : "+f"(c0), "+f"(c1), "+f"(c2), "+f"(c3)
        : "r"(a0), "r"(a1), "r"(a2), "r"(a3), "r"(b0), "r"(b1));
}

#define SPLAT2(out, f) asm("mov.b64 %0, {%1, %1};" : "=l"(out) : "r"(__float_as_uint(f)))
#define FMA2(acc, a, b) asm("fma.rn.f32x2 %0, %1, %2, %0;" : "+l"(acc) : "l"(a), "l"(b))
#define UNPACK2(lo, hi, in) asm("mov.b64 {%0, %1}, %2;" : "=r"(lo), "=r"(hi) : "l"(in))

// ---------------- prep: pack B frags + degree count ----------
__global__ void k_prep(const float* __restrict__ W1,
                       const int* __restrict__ dst, int* __restrict__ cnt) {
    int b = blockIdx.x, t = threadIdx.x;
    if (b < BPACK_BLOCKS) {
        int gid = b * 256 + t;
        int lane = gid & 31;
        int ntg = (gid >> 5) & 31;
        int ks = gid >> 10;
        int gr = lane >> 2, ct = lane & 3;
        int col = ntg * 8 + gr;
        int k0 = ks * 16 + 2 * ct;
        uint2 frag;
        frag.x = packh2(W1[k0 * 256 + col],       W1[(k0 + 1) * 256 + col]);
        frag.y = packh2(W1[(k0 + 8) * 256 + col], W1[(k0 + 9) * 256 + col]);
        g_w1p[(ks * 32 + ntg) * 32 + lane] = frag;
    } else {
        int gid = (b - BPACK_BLOCKS) * 256 + t;
        if (gid < EE / 4) {
            int4 d4 = ((const int4*)dst)[gid];
            atomicAdd(&cnt[d4.x], 1);
            atomicAdd(&cnt[d4.y], 1);
            atomicAdd(&cnt[d4.z], 1);
            atomicAdd(&cnt[d4.w], 1);
        }
    }
}

// ---------------- scan (+1 self-loop; zero pooling buffers) ----------------
__global__ void k_scan(const int* __restrict__ cnt, int* __restrict__ off,
                       int* __restrict__ cur, float* __restrict__ sums,
                       float* __restrict__ gcnt) {
    __shared__ int ssum[1024];
    const int CH = 20;
    int t = threadIdx.x;
    sums[t] = 0.f; sums[t + 1024] = 0.f;
    if (t < GG) gcnt[t] = 0.f;
    int base = t * CH;
    int local[CH];
    int s = 0;
#pragma unroll
    for (int j = 0; j < CH; j++) {
        int v = (base + j < NN) ? (cnt[base + j] + 1) : 0;
        local[j] = s;
        s += v;
    }
    ssum[t] = s;
    __syncthreads();
    for (int o = 1; o < 1024; o <<= 1) {
        int v = (t >= o) ? ssum[t - o] : 0;
        __syncthreads();
        ssum[t] += v;
        __syncthreads();
    }
    int pre = ssum[t] - s;
#pragma unroll
    for (int j = 0; j < CH; j++) {
        if (base + j < NN) { off[base + j] = pre + local[j]; cur[base + j] = pre + local[j]; }
    }
    if (t == 1023) off[NN] = ssum[1023];
}

// ------- fused: smem A-pack + tensor-core GEMM1 + att1  |  CSR build -------
__global__ void __launch_bounds__(256) k_mma_build(
        const float* __restrict__ x,
        const float* __restrict__ as1, const float* __restrict__ ad1,
        __half* __restrict__ h, float* __restrict__ asrc, float* __restrict__ adst,
        const int* __restrict__ src, const int* __restrict__ dst,
        int* __restrict__ cur, int* __restrict__ csr) {
    if (blockIdx.x >= MMA_BLOCKS) {
        int t = (blockIdx.x - MMA_BLOCKS) * 256 + threadIdx.x;
        if (t < EE / 4) {
            int4 s4 = ((const int4*)src)[t];
            int4 d4 = ((const int4*)dst)[t];
            csr[atomicAdd(&cur[d4.x], 1)] = s4.x;
            csr[atomicAdd(&cur[d4.y], 1)] = s4.y;
            csr[atomicAdd(&cur[d4.z], 1)] = s4.z;
            csr[atomicAdd(&cur[d4.w], 1)] = s4.w;
        } else {
            int n = t - EE / 4;
            if (n < NN) csr[atomicAdd(&cur[n], 1)] = n;
        }
        return;
    }

    __shared__ uint4 smA[2 * 8 * 32];          // A fragments for 2 m-tiles, 8 KB
    int bmt0 = blockIdx.x * 2;

    // phase 1: pack x -> fp16 fragments in smem (2 slots per thread)
    {
        const float2* x2 = (const float2*)x;
#pragma unroll
        for (int i = 0; i < 2; i++) {
            int slot = threadIdx.x + 256 * i;
            int lane = slot & 31;
            int ks = (slot >> 5) & 7;
            int mtl = slot >> 8;
            int gr = lane >> 2, ct = lane & 3;
            int r0 = (bmt0 + mtl) * 16 + gr;
            float2 p00 = x2[r0 * 64 + ks * 8 + ct];
            float2 p01 = x2[r0 * 64 + ks * 8 + ct + 4];
            float2 p10 = x2[(r0 + 8) * 64 + ks * 8 + ct];
            float2 p11 = x2[(r0 + 8) * 64 + ks * 8 + ct + 4];
            uint4 frag;
            frag.x = packh2(p00.x, p00.y);
            frag.y = packh2(p10.x, p10.y);
            frag.z = packh2(p01.x, p01.y);
            frag.w = packh2(p11.x, p11.y);
            smA[(mtl * 8 + ks) * 32 + lane] = frag;
        }
    }
    __syncthreads();

    int wid = threadIdx.x >> 5;
    int lane = threadIdx.x & 31;
    int mtl = wid >> 2;                         // 0..1
    int w = wid & 3;                            // head
    int mt = bmt0 + mtl;
    int gr = lane >> 2, ct = lane & 3;
    int row0 = mt * 16;

    uint4 a[8];
#pragma unroll
    for (int ks = 0; ks < 8; ks++) a[ks] = smA[(mtl * 8 + ks) * 32 + lane];

    float sr = 0.f, sr8 = 0.f, dr = 0.f, dr8 = 0.f;
    half2* h2out = (half2*)h;

#pragma unroll
    for (int nt = 0; nt < 8; nt++) {
        int ntg = w * 8 + nt;
        float c0 = 0.f, c1 = 0.f, c2 = 0.f, c3 = 0.f;
#pragma unroll
        for (int ks = 0; ks < 8; ks++) {
            uint2 bfr = g_w1p[(ks * 32 + ntg) * 32 + lane];
            mma16816(c0, c1, c2, c3, a[ks].x, a[ks].y, a[ks].z, a[ks].w,
                     bfr.x, bfr.y);
        }
        h2out[(row0 + gr) * 128 + w * 32 + nt * 4 + ct]     = __floats2half2_rn(c0, c1);
        h2out[(row0 + gr + 8) * 128 + w * 32 + nt * 4 + ct] = __floats2half2_rn(c2, c3);
        float2 av = ((const float2*)as1)[w * 32 + nt * 4 + ct];
        float2 dv = ((const float2*)ad1)[w * 32 + nt * 4 + ct];
        sr  += c0 * av.x + c1 * av.y;
        sr8 += c2 * av.x + c3 * av.y;
        dr  += c0 * dv.x + c1 * dv.y;
        dr8 += c2 * dv.x + c3 * dv.y;
    }
    sr  += __shfl_xor_sync(FULL, sr, 1);  sr  += __shfl_xor_sync(FULL, sr, 2);
    sr8 += __shfl_xor_sync(FULL, sr8, 1); sr8 += __shfl_xor_sync(FULL, sr8, 2);
    dr  += __shfl_xor_sync(FULL, dr, 1);  dr  += __shfl_xor_sync(FULL, dr, 2);
    dr8 += __shfl_xor_sync(FULL, dr8, 1); dr8 += __shfl_xor_sync(FULL, dr8, 2);
    if (ct == 0) {
        asrc[(row0 + gr) * 4 + w] = sr;
        asrc[(row0 + gr + 8) * 4 + w] = sr8;
        adst[(row0 + gr) * 4 + w] = dr;
        adst[(row0 + gr + 8) * 4 + w] = dr8;
    }
}

// ---------------- layer 1 aggregation -> x1 fp16 (high occupancy) ----------
__global__ void __launch_bounds__(256, 6) k_agg1(
        const int* __restrict__ off, const int* __restrict__ csr,
        const __half* __restrict__ hfeat, const float* __restrict__ asrc,
        const float* __restrict__ adst, const float* __restrict__ bias,
        __half* __restrict__ x1out) {
    __shared__ int    sm_s[8][32];
    __shared__ float4 sm_w[8][32];
    int wid = threadIdx.x >> 5;
    int lane = threadIdx.x & 31;
    int d = blockIdx.x * 8 + wid;
    if (d >= NN) return;
    int b0 = off[d], b1 = off[d + 1];

    float4 adv = ((const float4*)adst)[d];
    int hh = lane >> 3;

    float s0 = 0.f, s1 = 0.f, s2 = 0.f, s3 = 0.f;
    float acc[8];
#pragma unroll
    for (int j = 0; j < 8; j++) acc[j] = 0.f;

    const uint4* hf = (const uint4*)hfeat;
    const float4* as4 = (const float4*)asrc;
    const float* wp = (const float*)&sm_w[wid][0];

    for (int base = b0; base < b1; base += 32) {
        int k = base + lane;
        float4 w = make_float4(0.f, 0.f, 0.f, 0.f);
        int sidx = 0;
        if (k < b1) {
            sidx = csr[k];
            float4 a = as4[sidx];
            w.x = __expf(lrelu(a.x + adv.x));
            w.y = __expf(lrelu(a.y + adv.y));
            w.z = __expf(lrelu(a.z + adv.z));
            w.w = __expf(lrelu(a.w + adv.w));
            s0 += w.x; s1 += w.y; s2 += w.z; s3 += w.w;
        }
        sm_s[wid][lane] = sidx;
        sm_w[wid][lane] = w;
        __syncwarp();
        int cnt = min(32, b1 - base);
        for (int e = 0; e < cnt; e++) {
            int ss = sm_s[wid][e];
            float we = wp[e * 4 + hh];
            uint4 v = hf[ss * 32 + lane];
            float2 p;
            p = __half22float2(*(half2*)&v.x); acc[0] = fmaf(we, p.x, acc[0]); acc[1] = fmaf(we, p.y, acc[1]);
            p = __half22float2(*(half2*)&v.y); acc[2] = fmaf(we, p.x, acc[2]); acc[3] = fmaf(we, p.y, acc[3]);
            p = __half22float2(*(half2*)&v.z); acc[4] = fmaf(we, p.x, acc[4]); acc[5] = fmaf(we, p.y, acc[5]);
            p = __half22float2(*(half2*)&v.w); acc[6] = fmaf(we, p.x, acc[6]); acc[7] = fmaf(we, p.y, acc[7]);
        }
        __syncwarp();
    }

    s0 = warp_sum(s0); s1 = warp_sum(s1); s2 = warp_sum(s2); s3 = warp_sum(s3);
    float iH = (hh == 0) ? 1.f / (s0 + 1e-16f)
             : (hh == 1) ? 1.f / (s1 + 1e-16f)
             : (hh == 2) ? 1.f / (s2 + 1e-16f)
             :             1.f / (s3 + 1e-16f);
#pragma unroll
    for (int j = 0; j < 8; j++) acc[j] *= iH;

#pragma unroll
    for (int j = 0; j < 8; j++) {
        acc[j] += __shfl_xor_sync(FULL, acc[j], 8);
        acc[j] += __shfl_xor_sync(FULL, acc[j], 16);
    }
    if (lane < 8) {
        float4 bb0 = ((const float4*)bias)[lane * 2];
        float4 bb1 = ((const float4*)bias)[lane * 2 + 1];
        uint4 pk;
        pk.x = packh2(fmaxf(acc[0] * 0.25f + bb0.x, 0.f), fmaxf(acc[1] * 0.25f + bb0.y, 0.f));
        pk.y = packh2(fmaxf(acc[2] * 0.25f + bb0.z, 0.f), fmaxf(acc[3] * 0.25f + bb0.w, 0.f));
        pk.z = packh2(fmaxf(acc[4] * 0.25f + bb1.x, 0.f), fmaxf(acc[5] * 0.25f + bb1.y, 0.f));
        pk.w = packh2(fmaxf(acc[6] * 0.25f + bb1.z, 0.f), fmaxf(acc[7] * 0.25f + bb1.w, 0.f));
        ((uint4*)x1out)[d * 8 + lane] = pk;
    }
}

// ---------------- GEMM2: 128 nodes/block, 4-node W amortization ------------
__global__ void __launch_bounds__(256) k_gemm2(
        const __half* __restrict__ x1, const float* __restrict__ W2,
        const float* __restrict__ as2, const float* __restrict__ ad2,
        __half* __restrict__ h2out, float* __restrict__ asrc2,
        float* __restrict__ adst2) {
    __shared__ float  smW[64 * 64];
    __shared__ __half smX[128 * 68];
    int t = threadIdx.x;
    int n0 = blockIdx.x * 128;

#pragma unroll
    for (int i = 0; i < 4; i++)
        ((float4*)smW)[t + 256 * i] = ((const float4*)W2)[t + 256 * i];
    {
        int row = t >> 1, part = t & 1;
        int n = n0 + row;
        const uint4* gsrc = (const uint4*)x1 + (long long)n * 8 + part * 4;
        uint2* drow = (uint2*)(smX + row * 68 + part * 32);
#pragma unroll
        for (int i = 0; i < 4; i++) {
            uint4 v = (n < NN) ? gsrc[i] : make_uint4(0, 0, 0, 0);
            drow[2 * i]     = make_uint2(v.x, v.y);
            drow[2 * i + 1] = make_uint2(v.z, v.w);
        }
    }
    __syncthreads();

    int grp = t >> 3;
    int cg  = t & 7;
    int nl0 = grp * 4;

    unsigned long long acc[4][4];
#pragma unroll
    for (int r = 0; r < 4; r++)
#pragma unroll
        for (int j = 0; j < 4; j++) acc[r][j] = 0ull;

    const ulonglong2* Wr = (const ulonglong2*)smW;
#pragma unroll 4
    for (int k = 0; k < 64; k++) {
        ulonglong2 w0 = Wr[k * 16 + cg * 2];
        ulonglong2 w1 = Wr[k * 16 + cg * 2 + 1];
#pragma unroll
        for (int r = 0; r < 4; r++) {
            float xv = __half2float(smX[(nl0 + r) * 68 + k]);
            unsigned long long xs; SPLAT2(xs, xv);
            FMA2(acc[r][0], xs, w0.x); FMA2(acc[r][1], xs, w0.y);
            FMA2(acc[r][2], xs, w1.x); FMA2(acc[r][3], xs, w1.y);
        }
    }

    int hd = cg >> 2;
    const float4* a4 = (const float4*)(as2 + hd * 32 + (cg & 3) * 8);
    const float4* d4v = (const float4*)(ad2 + hd * 32 + (cg & 3) * 8);
    float4 aa0 = a4[0], aa1 = a4[1];
    float4 dd0 = d4v[0], dd1 = d4v[1];

#pragma unroll
    for (int r = 0; r < 4; r++) {
        int d = n0 + nl0 + r;
        float c[8];
        unsigned int lo, hi;
        UNPACK2(lo, hi, acc[r][0]); c[0] = __uint_as_float(lo); c[1] = __uint_as_float(hi);
        UNPACK2(lo, hi, acc[r][1]); c[2] = __uint_as_float(lo); c[3] = __uint_as_float(hi);
        UNPACK2(lo, hi, acc[r][2]); c[4] = __uint_as_float(lo); c[5] = __uint_as_float(hi);
        UNPACK2(lo, hi, acc[r][3]); c[6] = __uint_as_float(lo); c[7] = __uint_as_float(hi);
        float ps = c[0]*aa0.x + c[1]*aa0.y + c[2]*aa0.z + c[3]*aa0.w
                 + c[4]*aa1.x + c[5]*aa1.y + c[6]*aa1.z + c[7]*aa1.w;
        float pd = c[0]*dd0.x + c[1]*dd0.y + c[2]*dd0.z + c[3]*dd0.w
                 + c[4]*dd1.x + c[5]*dd1.y + c[6]*dd1.z + c[7]*dd1.w;
        ps += __shfl_xor_sync(FULL, ps, 1);
        ps += __shfl_xor_sync(FULL, ps, 2);
        pd += __shfl_xor_sync(FULL, pd, 1);
        pd += __shfl_xor_sync(FULL, pd, 2);
        if (d < NN) {
            uint4 pk;
            pk.x = packh2(c[0], c[1]);
            pk.y = packh2(c[2], c[3]);
            pk.z = packh2(c[4], c[5]);
            pk.w = packh2(c[6], c[7]);
            ((uint4*)h2out)[d * 8 + cg] = pk;
            if ((cg & 3) == 0) {
                asrc2[d * 2 + hd] = ps;
                adst2[d * 2 + hd] = pd;
            }
        }
    }
}

// ---------------- layer 2 aggregation + pool + fused heads -----------------
__global__ void __launch_bounds__(256, 6) k_agg2(
        const int* __restrict__ off, const int* __restrict__ csr,
        const __half* __restrict__ hfeat, const float* __restrict__ asrc,
        const float* __restrict__ adst, const float* __restrict__ bias,
        const int* __restrict__ batch, float* __restrict__ sums,
        float* __restrict__ gcnt,
        const float* __restrict__ cW1, const float* __restrict__ cb1,
        const float* __restrict__ cW2, const float* __restrict__ cb2,
        const float* __restrict__ hW1, const float* __restrict__ hb1,
        const float* __restrict__ hW2, const float* __restrict__ hb2,
        float* __restrict__ out, int* __restrict__ cntz,
        int* __restrict__ done) {
    __shared__ int    sm_s[8][32];
    __shared__ float2 sm_w[8][32];
    __shared__ int sm_last;
    int wid = threadIdx.x >> 5;
    int lane = threadIdx.x & 31;
    int d = blockIdx.x * 8 + wid;

    if (d < NN) {
        int b0 = off[d], b1 = off[d + 1];
        float2 adv = ((const float2*)adst)[d];
        int hh = lane >> 4;
        float s0 = 0.f, s1 = 0.f;
        float2 acc = make_float2(0.f, 0.f);
        const half2* hf = (const half2*)hfeat;
        const float2* as2p = (const float2*)asrc;
        const float* wp = (const float*)&sm_w[wid][0];

        for (int base = b0; base < b1; base += 32) {
            int k = base + lane;
            float2 w = make_float2(0.f, 0.f);
            int sidx = 0;
            if (k < b1) {
                sidx = csr[k];
                float2 a = as2p[sidx];
                w.x = __expf(lrelu(a.x + adv.x));
                w.y = __expf(lrelu(a.y + adv.y));
                s0 += w.x; s1 += w.y;
            }
            sm_s[wid][lane] = sidx;
            sm_w[wid][lane] = w;
            __syncwarp();
            int cnt = min(32, b1 - base);
            for (int e = 0; e < cnt; e++) {
                int ss = sm_s[wid][e];
                float we = wp[e * 2 + hh];
                float2 v = __half22float2(hf[ss * 32 + lane]);
                acc.x = fmaf(we, v.x, acc.x);
                acc.y = fmaf(we, v.y, acc.y);
            }
            __syncwarp();
        }

        s0 = warp_sum(s0); s1 = warp_sum(s1);
        float iH = hh ? 1.f / (s1 + 1e-16f) : 1.f / (s0 + 1e-16f);
        acc.x *= iH;
        acc.y *= iH;
        acc.x += __shfl_xor_sync(FULL, acc.x, 16);
        acc.y += __shfl_xor_sync(FULL, acc.y, 16);
        if (lane < 16) {
            const float2 b = ((const float2*)bias)[lane];
            float ox = fmaxf(acc.x * 0.5f + b.x, 0.f);
            float oy = fmaxf(acc.y * 0.5f + b.y, 0.f);
            int g = batch[d];
            atomicAdd(&sums[g * 32 + 2 * lane], ox);
            atomicAdd(&sums[g * 32 + 2 * lane + 1], oy);
            if (lane == 0) atomicAdd(&gcnt[g], 1.f);
        }
    }

    __threadfence();
    __syncthreads();
    if (threadIdx.x == 0)
        sm_last = (atomicAdd(done, 1) == gridDim.x - 1) ? 1 : 0;
    __syncthreads();
    if (!sm_last) return;

    int t = threadIdx.x;
    int4 z = make_int4(0, 0, 0, 0);
    for (int i = t; i < NN / 4; i += 256) ((int4*)cntz)[i] = z;
    if (t == 0) *done = 0;

    if (t < GG) {
        int g = t;
        float emb[32];
        float c_ = __ldcg(&gcnt[g]);
        c_ = (c_ > 1.f) ? c_ : 1.f;
        for (int c = 0; c < 32; c++) emb[c] = __ldcg(&sums[g * 32 + c]) / c_;
        float oh = hb2[0], oc = cb2[0];
        for (int j = 0; j < 16; j++) {
            float sh = hb1[j], sc = cb1[j];
            for (int c = 0; c < 32; c++) {
                sh = fmaf(emb[c], hW1[c * 16 + j], sh);
                sc = fmaf(emb[c], cW1[c * 16 + j], sc);
            }
            sh = fmaxf(sh, 0.f);
            sc = fmaxf(sc, 0.f);
            oh = fmaf(sh, hW2[j], oh);
            oc = fmaf(sc, cW2[j], oc);
        }
        out[g]      = 1.f / (1.f + __expf(-oh));
        out[GG + g] = 1.f / (1.f + __expf(-oc));
    }
}

// ---------------- host ----------------
static inline int cdiv(long long a, int b) { return (int)((a + b - 1) / b); }

extern "C" void kernel_launch(void* const* d_in, const int* in_sizes, int n_in,
                              void* d_out, int out_size) {
    const float* x     = (const float*)d_in[0];
    const int*   ei    = (const int*)  d_in[1];
    const int*   batch = (const int*)  d_in[2];
    const float* W1  = (const float*)d_in[3];
    const float* as1 = (const float*)d_in[4];
    const float* ad1 = (const float*)d_in[5];
    const float* b1  = (const float*)d_in[6];
    const float* W2  = (const float*)d_in[7];
    const float* as2 = (const float*)d_in[8];
    const float* ad2 = (const float*)d_in[9];
    const float* b2  = (const float*)d_in[10];
    const float* cW1 = (const float*)d_in[11];
    const float* cb1 = (const float*)d_in[12];
    const float* cW2 = (const float*)d_in[13];
    const float* cb2 = (const float*)d_in[14];
    const float* hW1 = (const float*)d_in[15];
    const float* hb1 = (const float*)d_in[16];
    const float* hW2 = (const float*)d_in[17];
    const float* hb2 = (const float*)d_in[18];

    const int* src = ei;
    const int* dst = ei + EE;

    __half *p_h, *p_x1, *p_h2;
    float *p_asrc, *p_adst, *p_asrc2, *p_adst2, *p_sums, *p_gcnt;
    int *p_cnt, *p_off, *p_cur, *p_csr, *p_done;
    cudaGetSymbolAddress((void**)&p_h, g_h);
    cudaGetSymbolAddress((void**)&p_x1, g_x1);
    cudaGetSymbolAddress((void**)&p_h2, g_h2);
    cudaGetSymbolAddress((void**)&p_asrc, g_asrc);
    cudaGetSymbolAddress((void**)&p_adst, g_adst);
    cudaGetSymbolAddress((void**)&p_asrc2, g_asrc2);
    cudaGetSymbolAddress((void**)&p_adst2, g_adst2);
    cudaGetSymbolAddress((void**)&p_cnt, g_cnt);
    cudaGetSymbolAddress((void**)&p_off, g_off);
    cudaGetSymbolAddress((void**)&p_cur, g_cur);
    cudaGetSymbolAddress((void**)&p_csr, g_csr);
    cudaGetSymbolAddress((void**)&p_sums, g_sums);
    cudaGetSymbolAddress((void**)&p_gcnt, g_gcnt);
    cudaGetSymbolAddress((void**)&p_done, g_done);

    const int T = 256;

    k_prep<<<BPACK_BLOCKS + COUNT_BLOCKS, T>>>(W1, dst, p_cnt);
    k_scan<<<1, 1024>>>(p_cnt, p_off, p_cur, p_sums, p_gcnt);
    k_mma_build<<<MMA_BLOCKS + BUILD_BLOCKS, T>>>(x, as1, ad1, p_h, p_asrc, p_adst,
                                                  src, dst, p_cur, p_csr);
    k_agg1<<<AGG_BLOCKS, T>>>(p_off, p_csr, p_h, p_asrc, p_adst, b1, p_x1);
    k_gemm2<<<cdiv(NN, 128), T>>>(p_x1, W2, as2, ad2, p_h2, p_asrc2, p_adst2);
    k_agg2<<<AGG_BLOCKS, T>>>(p_off, p_csr, p_h2, p_asrc2, p_adst2, b2,
                              batch, p_sums, p_gcnt,
                              cW1, cb1, cW2, cb2, hW1, hb1, hW2, hb2,
                              (float*)d_out, p_cnt, p_done);
}